// round 5
// baseline (speedup 1.0000x reference)
#include <cuda_runtime.h>
#include <math.h>
#include <stdint.h>

// ---------------- problem dims ----------------
#define BATCH   8
#define SEQ     512
#define NTOK    4096
#define DMODEL  1024
#define NHEAD   16
#define DHEAD   64
#define DFF     4096
#define NLAYER  6
#define KVW     2048

// ---------------- scratch ----------------
__device__ float g_x  [(size_t)NTOK * DMODEL];
__device__ float g_q  [(size_t)NTOK * DMODEL];
__device__ float g_kv [(size_t)NTOK * KVW];
__device__ float g_sc [(size_t)BATCH * NHEAD * SEQ * SEQ];
__device__ float g_pe [(size_t)SEQ * DMODEL];
__device__ float g_ffn[(size_t)NTOK * DFF];

// int8 activation digits + per-row scales
__device__ int8_t g_h0[(size_t)NTOK * DMODEL];
__device__ int8_t g_h1[(size_t)NTOK * DMODEL];
__device__ int8_t g_o0[(size_t)NTOK * DMODEL];
__device__ int8_t g_o1[(size_t)NTOK * DMODEL];
__device__ int8_t g_f0[(size_t)NTOK * DFF];
__device__ int8_t g_f1[(size_t)NTOK * DFF];
__device__ float  g_sh[NTOK];
__device__ float  g_so[NTOK];
__device__ float  g_sf[NTOK];

// int8 weight digits [N,K] (transposed) + per-col scales
__device__ int8_t g_wq0 [(size_t)NLAYER * DMODEL * DMODEL];
__device__ int8_t g_wq1 [(size_t)NLAYER * DMODEL * DMODEL];
__device__ int8_t g_wkv0[(size_t)NLAYER * DMODEL * KVW];
__device__ int8_t g_wkv1[(size_t)NLAYER * DMODEL * KVW];
__device__ int8_t g_wo0 [(size_t)NLAYER * DMODEL * DMODEL];
__device__ int8_t g_wo1 [(size_t)NLAYER * DMODEL * DMODEL];
__device__ int8_t g_w10 [(size_t)NLAYER * DMODEL * DFF];
__device__ int8_t g_w11 [(size_t)NLAYER * DMODEL * DFF];
__device__ int8_t g_w20 [(size_t)NLAYER * DFF * DMODEL];
__device__ int8_t g_w21 [(size_t)NLAYER * DFF * DMODEL];
__device__ float  g_swq [(size_t)NLAYER * DMODEL];
__device__ float  g_swkv[(size_t)NLAYER * KVW];
__device__ float  g_swo [(size_t)NLAYER * DMODEL];
__device__ float  g_sw1 [(size_t)NLAYER * DFF];
__device__ float  g_sw2 [(size_t)NLAYER * DMODEL];

// ---------------- helpers ----------------
__device__ __forceinline__ uint32_t smem_u32(const void* p) {
    uint32_t a;
    asm("{ .reg .u64 t; cvta.to.shared.u64 t, %1; cvt.u32.u64 %0, t; }" : "=r"(a) : "l"(p));
    return a;
}
#define CP_ASYNC16(dst, src) \
    asm volatile("cp.async.cg.shared.global [%0], [%1], 16;" :: "r"(dst), "l"(src) : "memory")
#define CP_COMMIT() asm volatile("cp.async.commit_group;" ::: "memory")
#define CP_WAIT2()  asm volatile("cp.async.wait_group 2;" ::: "memory")
#define CP_WAIT1()  asm volatile("cp.async.wait_group 1;" ::: "memory")
#define CP_WAIT0()  asm volatile("cp.async.wait_group 0;" ::: "memory")

__device__ __forceinline__ void ldsm4(uint32_t* r, uint32_t addr) {
    asm volatile("ldmatrix.sync.aligned.m8n8.x4.shared.b16 {%0,%1,%2,%3}, [%4];"
        : "=r"(r[0]), "=r"(r[1]), "=r"(r[2]), "=r"(r[3]) : "r"(addr));
}
__device__ __forceinline__ void mma_s8(int* d, const uint32_t* a, const uint32_t* b) {
    asm volatile("mma.sync.aligned.m16n8k32.row.col.s32.s8.s8.s32 "
        "{%0,%1,%2,%3}, {%4,%5,%6,%7}, {%8,%9}, {%0,%1,%2,%3};"
        : "+r"(d[0]), "+r"(d[1]), "+r"(d[2]), "+r"(d[3])
        : "r"(a[0]), "r"(a[1]), "r"(a[2]), "r"(a[3]), "r"(b[0]), "r"(b[1]));
}

// ---------------- int8 GEMM: C[M,N] = sa_r*sw_c*(A@Bt^T) + bias ----------------
// CTA 128x128, 8 warps (2x4), warp 64x32. BK=64 int8. 3-stage cp.async.
// digits: acc0 = a0*w0 ; acc1 = a0*w1 + a1*w0 (scaled 1/128 in epilogue).
// MODE 0: fp32+bias; 1: +residual; 2: relu fp32
#define I8_ROWB  80
#define I8_PLANE 10240
#define I8_STAGE 40960
#define I8_SMEM  (3 * I8_STAGE)

template <int MODE>
__global__ void __launch_bounds__(256) tgemm_i8(const int8_t* __restrict__ A0, const int8_t* __restrict__ A1,
                                                const float* __restrict__ saA,
                                                const int8_t* __restrict__ B0, const int8_t* __restrict__ B1,
                                                const float* __restrict__ swB,
                                                const float* __restrict__ bias,
                                                float* __restrict__ Cf,
                                                int N, int K) {
    extern __shared__ char smem[];
    const uint32_t sb = smem_u32(smem);
    const int tid  = threadIdx.x;
    const int wid  = tid >> 5, lane = tid & 31;
    const int wm   = wid >> 2, wn = wid & 3;    // 2 x 4 warps, warp tile 64x32
    const int bm   = blockIdx.y << 7;
    const int bn   = blockIdx.x << 7;
    const int T    = K >> 6;

    int acc0[4][4][4] = {};
    int acc1[4][4][4] = {};

    auto load_stage = [&](int sidx, int k0) {
        uint32_t stg = sb + sidx * I8_STAGE;
#pragma unroll
        for (int i = 0; i < 8; i++) {
            int flat  = tid + i * 256;          // 0..2047
            int plane = flat >> 9;              // 0:A0 1:A1 2:B0 3:B1
            int idx   = flat & 511;
            int r = idx >> 2, c = idx & 3;
            const int8_t* base = (plane == 0) ? A0 : (plane == 1) ? A1 : (plane == 2) ? B0 : B1;
            int rowg = ((plane < 2) ? bm : bn) + r;
            const int8_t* src = base + (size_t)rowg * K + k0 + c * 16;
            CP_ASYNC16(stg + plane * I8_PLANE + r * I8_ROWB + c * 16, src);
        }
        CP_COMMIT();
    };

    load_stage(0, 0);
    load_stage(1, 64);

    const int xr = lane & 15;
    const int xc = (lane >> 4) * 16;

    for (int it = 0; it < T; it++) {
        if (it + 2 < T) load_stage((it + 2) % 3, (it + 2) << 6);
        int remain = T - 1 - it;
        if (remain >= 2)      { CP_WAIT2(); }
        else if (remain == 1) { CP_WAIT1(); }
        else                  { CP_WAIT0(); }
        __syncthreads();

        uint32_t stg = sb + (it % 3) * I8_STAGE;
        uint32_t aB = stg + (wm * 64 + xr) * I8_ROWB + xc;
        uint32_t bB = stg + 2 * I8_PLANE + (wn * 32 + xr) * I8_ROWB + xc;

#pragma unroll
        for (int kk = 0; kk < 2; kk++) {
            uint32_t ka = kk * 32;
            uint32_t a0f[4][4], a1f[4][4], b0f[4][2], b1f[4][2];
#pragma unroll
            for (int mi = 0; mi < 4; mi++) {
                ldsm4(a0f[mi], aB + mi * 16 * I8_ROWB + ka);
                ldsm4(a1f[mi], aB + I8_PLANE + mi * 16 * I8_ROWB + ka);
            }
#pragma unroll
            for (int g = 0; g < 2; g++) {
                uint32_t r4[4];
                ldsm4(r4, bB + g * 16 * I8_ROWB + ka);
                b0f[g * 2][0] = r4[0]; b0f[g * 2][1] = r4[2];
                b0f[g * 2 + 1][0] = r4[1]; b0f[g * 2 + 1][1] = r4[3];
                ldsm4(r4, bB + I8_PLANE + g * 16 * I8_ROWB + ka);
                b1f[g * 2][0] = r4[0]; b1f[g * 2][1] = r4[2];
                b1f[g * 2 + 1][0] = r4[1]; b1f[g * 2 + 1][1] = r4[3];
            }
#pragma unroll
            for (int mi = 0; mi < 4; mi++)
#pragma unroll
                for (int ni = 0; ni < 4; ni++) {
                    mma_s8(acc0[mi][ni], a0f[mi], b0f[ni]);
                    mma_s8(acc1[mi][ni], a0f[mi], b1f[ni]);
                    mma_s8(acc1[mi][ni], a1f[mi], b0f[ni]);
                }
        }
        __syncthreads();
    }

    // epilogue
#pragma unroll
    for (int mi = 0; mi < 4; mi++) {
        int rbase = bm + wm * 64 + mi * 16 + (lane >> 2);
        float sa0 = saA[rbase], sa1 = saA[rbase + 8];
#pragma unroll
        for (int ni = 0; ni < 4; ni++) {
            int col = bn + wn * 32 + ni * 8 + (lane & 3) * 2;
            float sw0 = swB[col], sw1 = swB[col + 1];
            float bv0 = bias[col], bv1 = bias[col + 1];
#pragma unroll
            for (int half = 0; half < 2; half++) {
                int row = rbase + half * 8;
                float sa = half ? sa1 : sa0;
                float u0 = (float)acc0[mi][ni][half * 2]     + (float)acc1[mi][ni][half * 2]     * 0.0078125f;
                float u1 = (float)acc0[mi][ni][half * 2 + 1] + (float)acc1[mi][ni][half * 2 + 1] * 0.0078125f;
                float v0 = sa * sw0 * u0 + bv0;
                float v1 = sa * sw1 * u1 + bv1;
                float* dst = Cf + (size_t)row * N + col;
                if (MODE == 1) { v0 += dst[0]; v1 += dst[1]; }
                if (MODE == 2) { v0 = fmaxf(v0, 0.f); v1 = fmaxf(v1, 0.f); }
                float2 o; o.x = v0; o.y = v1;
                *(float2*)dst = o;
            }
        }
    }
}

// ---------------- per-output-column weight amax: W[K,N] -> sw[n]=amax/127 ----------------
__global__ void wamax(const float* __restrict__ W, float* __restrict__ sw, int K, int N) {
    int l = blockIdx.y;
    int n = blockIdx.x * 32 + threadIdx.x;
    const float* Wl = W + (size_t)l * K * N;
    int kpt = K >> 3;
    float am = 0.f;
    int k0 = threadIdx.y * kpt;
    for (int k = k0; k < k0 + kpt; k++)
        am = fmaxf(am, fabsf(Wl[(size_t)k * N + n]));
    __shared__ float red[8][33];
    red[threadIdx.y][threadIdx.x] = am;
    __syncthreads();
    if (threadIdx.y == 0) {
#pragma unroll
        for (int j = 1; j < 8; j++) am = fmaxf(am, red[j][threadIdx.x]);
        sw[(size_t)l * N + n] = fmaxf(am, 1e-30f) * (1.f / 127.f);
    }
}

// ---------------- weight transpose + 2-digit int8 quant: W[K,N] -> [N,K] ----------------
__global__ void wquant(const float* __restrict__ W, const float* __restrict__ sw,
                       int8_t* __restrict__ T0, int8_t* __restrict__ T1, int K, int N) {
    __shared__ float t[32][33];
    int l = blockIdx.z;
    const float* Wl = W + (size_t)l * K * N;
    int8_t* o0 = T0 + (size_t)l * K * N;
    int8_t* o1 = T1 + (size_t)l * K * N;
    int k0 = blockIdx.y << 5, n0 = blockIdx.x << 5;
    int tx = threadIdx.x, ty = threadIdx.y;
#pragma unroll
    for (int i = 0; i < 4; i++)
        t[ty + i * 8][tx] = Wl[(size_t)(k0 + ty + i * 8) * N + n0 + tx];
    __syncthreads();
#pragma unroll
    for (int i = 0; i < 4; i++) {
        int n = n0 + ty + i * 8;
        float s = sw[(size_t)l * N + n];
        float q = t[tx][ty + i * 8] / s;
        float q0 = rintf(q);
        q0 = fminf(fmaxf(q0, -127.f), 127.f);
        float q1 = rintf((q - q0) * 128.f);
        q1 = fminf(fmaxf(q1, -127.f), 127.f);
        size_t di = (size_t)n * K + k0 + tx;
        o0[di] = (int8_t)(int)q0;
        o1[di] = (int8_t)(int)q1;
    }
}

// ---------------- per-row 2-digit quantizer (fp32 -> int8 digits + scale) ----------------
__global__ void __launch_bounds__(256) quant_rows(const float* __restrict__ in,
                                                  int8_t* __restrict__ d0, int8_t* __restrict__ d1,
                                                  float* __restrict__ sc, int width) {
    int row = blockIdx.x;
    const float* r = in + (size_t)row * width;
    int per = width >> 8;
    float v[16];
    float am = 0.f;
    for (int i = 0; i < per; i++) {
        v[i] = r[threadIdx.x + i * 256];
        am = fmaxf(am, fabsf(v[i]));
    }
    __shared__ float ram[8];
#pragma unroll
    for (int off = 16; off; off >>= 1) am = fmaxf(am, __shfl_xor_sync(0xffffffffu, am, off));
    if ((threadIdx.x & 31) == 0) ram[threadIdx.x >> 5] = am;
    __syncthreads();
    if (threadIdx.x < 32) {
        am = (threadIdx.x < 8) ? ram[threadIdx.x] : 0.f;
#pragma unroll
        for (int off = 4; off; off >>= 1) am = fmaxf(am, __shfl_xor_sync(0xffffffffu, am, off));
        if (threadIdx.x == 0) ram[0] = fmaxf(am, 1e-30f);
    }
    __syncthreads();
    float amax = ram[0];
    float inv = 127.f / amax;
    if (threadIdx.x == 0) sc[row] = amax * (1.f / 127.f);
    for (int i = 0; i < per; i++) {
        int c = threadIdx.x + i * 256;
        float q = v[i] * inv;
        float q0 = rintf(q);
        q0 = fminf(fmaxf(q0, -127.f), 127.f);
        float q1 = rintf((q - q0) * 128.f);
        q1 = fminf(fmaxf(q1, -127.f), 127.f);
        d0[(size_t)row * width + c] = (int8_t)(int)q0;
        d1[(size_t)row * width + c] = (int8_t)(int)q1;
    }
}

// ---------------- positional encoding ----------------
__global__ void pe_kernel(float* __restrict__ pe) {
    int idx = blockIdx.x * 256 + threadIdx.x;
    if (idx >= SEQ * DMODEL) return;
    int s = idx >> 10;
    int d = idx & 1023;
    double e = (double)(2 * (d >> 1)) / 1024.0;
    double ang = (double)s * exp(-e * log(10000.0));
    pe[idx] = (d & 1) ? (float)cos(ang) : (float)sin(ang);
}

// ---------------- embedding + PE ----------------
__global__ void embed_kernel(const int* __restrict__ tokens, const float* __restrict__ emb,
                             const float* __restrict__ pe, float* __restrict__ x) {
    int idx = blockIdx.x * 256 + threadIdx.x;
    if (idx >= NTOK * DMODEL) return;
    int row = idx >> 10;
    int d = idx & 1023;
    int s = row & (SEQ - 1);
    x[idx] = emb[(size_t)tokens[row] * DMODEL + d] * 32.0f + pe[(s << 10) + d];
}

// ---------------- layernorm (QUANT=1 -> int8 digits + row scale; 0 -> fp32) ----------------
template <int QUANT>
__global__ void __launch_bounds__(256) ln_kernel(const float* __restrict__ in,
                                                 const float* __restrict__ g,
                                                 const float* __restrict__ b,
                                                 float* __restrict__ outf,
                                                 int8_t* __restrict__ d0, int8_t* __restrict__ d1,
                                                 float* __restrict__ sc) {
    int row = blockIdx.x;
    const float* xr = in + (size_t)row * DMODEL;
    float v[4];
    float s = 0.f, s2 = 0.f;
#pragma unroll
    for (int i = 0; i < 4; i++) {
        v[i] = xr[threadIdx.x + i * 256];
        s += v[i]; s2 += v[i] * v[i];
    }
    __shared__ float rs[8], rs2[8], ram[8];
#pragma unroll
    for (int off = 16; off; off >>= 1) {
        s  += __shfl_xor_sync(0xffffffffu, s, off);
        s2 += __shfl_xor_sync(0xffffffffu, s2, off);
    }
    if ((threadIdx.x & 31) == 0) { rs[threadIdx.x >> 5] = s; rs2[threadIdx.x >> 5] = s2; }
    __syncthreads();
    if (threadIdx.x < 32) {
        s  = (threadIdx.x < 8) ? rs[threadIdx.x] : 0.f;
        s2 = (threadIdx.x < 8) ? rs2[threadIdx.x] : 0.f;
#pragma unroll
        for (int off = 4; off; off >>= 1) {
            s  += __shfl_xor_sync(0xffffffffu, s, off);
            s2 += __shfl_xor_sync(0xffffffffu, s2, off);
        }
        if (threadIdx.x == 0) { rs[0] = s; rs2[0] = s2; }
    }
    __syncthreads();
    float m = rs[0] * (1.f / DMODEL);
    float var = rs2[0] * (1.f / DMODEL) - m * m;
    float rstd = rsqrtf(var + 1e-5f);

    float val[4];
    float am = 0.f;
#pragma unroll
    for (int i = 0; i < 4; i++) {
        int c = threadIdx.x + i * 256;
        val[i] = (v[i] - m) * rstd * g[c] + b[c];
        am = fmaxf(am, fabsf(val[i]));
    }
    if (QUANT) {
#pragma unroll
        for (int off = 16; off; off >>= 1) am = fmaxf(am, __shfl_xor_sync(0xffffffffu, am, off));
        if ((threadIdx.x & 31) == 0) ram[threadIdx.x >> 5] = am;
        __syncthreads();
        if (threadIdx.x < 32) {
            am = (threadIdx.x < 8) ? ram[threadIdx.x] : 0.f;
#pragma unroll
            for (int off = 4; off; off >>= 1) am = fmaxf(am, __shfl_xor_sync(0xffffffffu, am, off));
            if (threadIdx.x == 0) ram[0] = fmaxf(am, 1e-30f);
        }
        __syncthreads();
        float amax = ram[0];
        float inv = 127.f / amax;
        if (threadIdx.x == 0) sc[row] = amax * (1.f / 127.f);
#pragma unroll
        for (int i = 0; i < 4; i++) {
            int c = threadIdx.x + i * 256;
            float q = val[i] * inv;
            float q0 = rintf(q);
            q0 = fminf(fmaxf(q0, -127.f), 127.f);
            float q1 = rintf((q - q0) * 128.f);
            q1 = fminf(fmaxf(q1, -127.f), 127.f);
            d0[(size_t)row * DMODEL + c] = (int8_t)(int)q0;
            d1[(size_t)row * DMODEL + c] = (int8_t)(int)q1;
        }
    } else {
#pragma unroll
        for (int i = 0; i < 4; i++) {
            int c = threadIdx.x + i * 256;
            outf[(size_t)row * DMODEL + c] = val[i];
        }
    }
}

// ---------------- scores ----------------
__global__ void __launch_bounds__(256) scores_kernel(const float* __restrict__ q,
                                                     const float* __restrict__ kv,
                                                     float* __restrict__ sc) {
    int bh = blockIdx.z;
    int b = bh >> 4, h = bh & 15;
    int qi0 = blockIdx.y << 6, ki0 = blockIdx.x << 6;
    __shared__ float Qs[16][68], Ks[16][68];
    int tid = threadIdx.x;
    int tx = tid & 15, ty = tid >> 4;
    float acc[4][4] = {};
    const float* qbase = q  + ((size_t)(b * SEQ) + qi0) * DMODEL + h * DHEAD;
    const float* kbase = kv + ((size_t)(b * SEQ) + ki0) * KVW + h * DHEAD;
    int lr = tid >> 2, lc = (tid & 3) << 2;
    for (int d0 = 0; d0 < DHEAD; d0 += 16) {
        float4 qv = *(const float4*)(qbase + (size_t)lr * DMODEL + d0 + lc);
        Qs[lc + 0][lr] = qv.x; Qs[lc + 1][lr] = qv.y; Qs[lc + 2][lr] = qv.z; Qs[lc + 3][lr] = qv.w;
        float4 kk = *(const float4*)(kbase + (size_t)lr * KVW + d0 + lc);
        Ks[lc + 0][lr] = kk.x; Ks[lc + 1][lr] = kk.y; Ks[lc + 2][lr] = kk.z; Ks[lc + 3][lr] = kk.w;
        __syncthreads();
#pragma unroll
        for (int k = 0; k < 16; k++) {
            float ra[4], rb[4];
#pragma unroll
            for (int i = 0; i < 4; i++) ra[i] = Qs[k][ty * 4 + i];
#pragma unroll
            for (int j = 0; j < 4; j++) rb[j] = Ks[k][tx * 4 + j];
#pragma unroll
            for (int i = 0; i < 4; i++)
#pragma unroll
                for (int j = 0; j < 4; j++)
                    acc[i][j] = fmaf(ra[i], rb[j], acc[i][j]);
        }
        __syncthreads();
    }
#pragma unroll
    for (int i = 0; i < 4; i++) {
        float* srow = sc + ((size_t)bh * SEQ + qi0 + ty * 4 + i) * SEQ + ki0 + tx * 4;
        *(float4*)srow = make_float4(acc[i][0] * 0.125f, acc[i][1] * 0.125f,
                                     acc[i][2] * 0.125f, acc[i][3] * 0.125f);
    }
}

// ---------------- masked softmax ----------------
__global__ void __launch_bounds__(256) softmax_kernel(float* __restrict__ sc,
                                                      const int* __restrict__ lengths) {
    int gw = (blockIdx.x * blockDim.x + threadIdx.x) >> 5;
    int lane = threadIdx.x & 31;
    if (gw >= BATCH * NHEAD * SEQ) return;
    int b = gw >> 13;
    int len = lengths[b];
    float* row = sc + (size_t)gw * SEQ;
    float v[16];
    float mx = -1e30f;
#pragma unroll
    for (int i = 0; i < 16; i++) {
        int c = lane + i * 32;
        v[i] = (c < len) ? row[c] : -1e30f;
        mx = fmaxf(mx, v[i]);
    }
#pragma unroll
    for (int off = 16; off; off >>= 1) mx = fmaxf(mx, __shfl_xor_sync(0xffffffffu, mx, off));
    float s = 0.f;
#pragma unroll
    for (int i = 0; i < 16; i++) {
        int c = lane + i * 32;
        v[i] = (c < len) ? __expf(v[i] - mx) : 0.f;
        s += v[i];
    }
#pragma unroll
    for (int off = 16; off; off >>= 1) s += __shfl_xor_sync(0xffffffffu, s, off);
    float inv = 1.f / s;
#pragma unroll
    for (int i = 0; i < 16; i++) row[lane + i * 32] = v[i] * inv;
}

// ---------------- AV -> fp32 o ----------------
__global__ void __launch_bounds__(256) av_kernel(const float* __restrict__ sc,
                                                 const float* __restrict__ kv,
                                                 float* __restrict__ o) {
    int bh = blockIdx.z;
    int b = bh >> 4, h = bh & 15;
    int qi0 = blockIdx.y << 6;
    __shared__ float Ps[16][68], Vs[16][68];
    int tid = threadIdx.x;
    int tx = tid & 15, ty = tid >> 4;
    float acc[4][4] = {};
    const float* prow = sc + ((size_t)bh * SEQ + qi0) * SEQ;
    const float* vbase = kv + (size_t)b * SEQ * KVW + NHEAD * DHEAD + h * DHEAD;
    int lr = tid >> 2, lc = (tid & 3) << 2;
    int vr = tid >> 4, vc = (tid & 15) << 2;
    for (int k0 = 0; k0 < SEQ; k0 += 16) {
        float4 pv = *(const float4*)(prow + (size_t)lr * SEQ + k0 + lc);
        Ps[lc + 0][lr] = pv.x; Ps[lc + 1][lr] = pv.y; Ps[lc + 2][lr] = pv.z; Ps[lc + 3][lr] = pv.w;
        *(float4*)&Vs[vr][vc] = *(const float4*)(vbase + (size_t)(k0 + vr) * KVW + vc);
        __syncthreads();
#pragma unroll
        for (int k = 0; k < 16; k++) {
            float ra[4], rb[4];
#pragma unroll
            for (int i = 0; i < 4; i++) ra[i] = Ps[k][ty * 4 + i];
#pragma unroll
            for (int j = 0; j < 4; j++) rb[j] = Vs[k][tx * 4 + j];
#pragma unroll
            for (int i = 0; i < 4; i++)
#pragma unroll
                for (int j = 0; j < 4; j++)
                    acc[i][j] = fmaf(ra[i], rb[j], acc[i][j]);
        }
        __syncthreads();
    }
#pragma unroll
    for (int i = 0; i < 4; i++) {
        float* orow = o + ((size_t)(b * SEQ) + qi0 + ty * 4 + i) * DMODEL + h * DHEAD + tx * 4;
        *(float4*)orow = make_float4(acc[i][0], acc[i][1], acc[i][2], acc[i][3]);
    }
}

// ---------------- host ----------------
extern "C" void kernel_launch(void* const* d_in, const int* in_sizes, int n_in,
                              void* d_out, int out_size) {
    const int*   tokens = (const int*)  d_in[0];
    const int*   lengths= (const int*)  d_in[1];
    const float* emb    = (const float*)d_in[2];
    const float* Wq     = (const float*)d_in[3];
    const float* bq     = (const float*)d_in[4];
    const float* Wkv    = (const float*)d_in[5];
    const float* bkv    = (const float*)d_in[6];
    const float* Wo     = (const float*)d_in[7];
    const float* bo     = (const float*)d_in[8];
    const float* lag    = (const float*)d_in[9];
    const float* lab    = (const float*)d_in[10];
    const float* W1     = (const float*)d_in[11];
    const float* b1     = (const float*)d_in[12];
    const float* W2     = (const float*)d_in[13];
    const float* b2     = (const float*)d_in[14];
    const float* lfg    = (const float*)d_in[15];
    const float* lfb    = (const float*)d_in[16];
    const float* lng    = (const float*)d_in[17];
    const float* lnb    = (const float*)d_in[18];

    float *x, *q, *kv, *sc, *pe, *ffn;
    int8_t *h0, *h1, *o0, *o1, *f0, *f1;
    float *sh, *so, *sf;
    int8_t *wq0, *wq1, *wkv0, *wkv1, *wo0, *wo1, *w10, *w11, *w20, *w21;
    float *swq, *swkv, *swo, *sw1, *sw2;
    cudaGetSymbolAddress((void**)&x, g_x);
    cudaGetSymbolAddress((void**)&q, g_q);
    cudaGetSymbolAddress((void**)&kv, g_kv);
    cudaGetSymbolAddress((void**)&sc, g_sc);
    cudaGetSymbolAddress((void**)&pe, g_pe);
    cudaGetSymbolAddress((void**)&ffn, g_ffn);
    cudaGetSymbolAddress((void**)&h0, g_h0); cudaGetSymbolAddress((void**)&h1, g_h1);
    cudaGetSymbolAddress((void**)&o0, g_o0); cudaGetSymbolAddress((void**)&o1, g_o1);
    cudaGetSymbolAddress((void**)&f0, g_f0); cudaGetSymbolAddress((void**)&f1, g_f1);
    cudaGetSymbolAddress((void**)&sh, g_sh); cudaGetSymbolAddress((void**)&so, g_so);
    cudaGetSymbolAddress((void**)&sf, g_sf);
    cudaGetSymbolAddress((void**)&wq0, g_wq0);   cudaGetSymbolAddress((void**)&wq1, g_wq1);
    cudaGetSymbolAddress((void**)&wkv0, g_wkv0); cudaGetSymbolAddress((void**)&wkv1, g_wkv1);
    cudaGetSymbolAddress((void**)&wo0, g_wo0);   cudaGetSymbolAddress((void**)&wo1, g_wo1);
    cudaGetSymbolAddress((void**)&w10, g_w10);   cudaGetSymbolAddress((void**)&w11, g_w11);
    cudaGetSymbolAddress((void**)&w20, g_w20);   cudaGetSymbolAddress((void**)&w21, g_w21);
    cudaGetSymbolAddress((void**)&swq, g_swq);   cudaGetSymbolAddress((void**)&swkv, g_swkv);
    cudaGetSymbolAddress((void**)&swo, g_swo);   cudaGetSymbolAddress((void**)&sw1, g_sw1);
    cudaGetSymbolAddress((void**)&sw2, g_sw2);

    cudaFuncSetAttribute(tgemm_i8<0>, cudaFuncAttributeMaxDynamicSharedMemorySize, I8_SMEM);
    cudaFuncSetAttribute(tgemm_i8<1>, cudaFuncAttributeMaxDynamicSharedMemorySize, I8_SMEM);
    cudaFuncSetAttribute(tgemm_i8<2>, cudaFuncAttributeMaxDynamicSharedMemorySize, I8_SMEM);

    dim3 wb(32, 8);
    // weight scales
    wamax<<<dim3(DMODEL / 32, NLAYER), wb>>>(Wq,  swq,  DMODEL, DMODEL);
    wamax<<<dim3(KVW / 32,    NLAYER), wb>>>(Wkv, swkv, DMODEL, KVW);
    wamax<<<dim3(DMODEL / 32, NLAYER), wb>>>(Wo,  swo,  DMODEL, DMODEL);
    wamax<<<dim3(DFF / 32,    NLAYER), wb>>>(W1,  sw1,  DMODEL, DFF);
    wamax<<<dim3(DMODEL / 32, NLAYER), wb>>>(W2,  sw2,  DFF,    DMODEL);
    // weight digits (transposed)
    wquant<<<dim3(DMODEL / 32, DMODEL / 32, NLAYER), wb>>>(Wq,  swq,  wq0,  wq1,  DMODEL, DMODEL);
    wquant<<<dim3(KVW / 32,    DMODEL / 32, NLAYER), wb>>>(Wkv, swkv, wkv0, wkv1, DMODEL, KVW);
    wquant<<<dim3(DMODEL / 32, DMODEL / 32, NLAYER), wb>>>(Wo,  swo,  wo0,  wo1,  DMODEL, DMODEL);
    wquant<<<dim3(DFF / 32,    DMODEL / 32, NLAYER), wb>>>(W1,  sw1,  w10,  w11,  DMODEL, DFF);
    wquant<<<dim3(DMODEL / 32, DFF / 32,    NLAYER), wb>>>(W2,  sw2,  w20,  w21,  DFF,    DMODEL);

    pe_kernel<<<(SEQ * DMODEL) / 256, 256>>>(pe);
    embed_kernel<<<(NTOK * DMODEL) / 256, 256>>>(tokens, emb, pe, x);

    for (int l = 0; l < NLAYER; l++) {
        size_t oQ  = (size_t)l * DMODEL * DMODEL;
        size_t oKV = (size_t)l * DMODEL * KVW;
        size_t o1w = (size_t)l * DMODEL * DFF;

        // attention sublayer
        ln_kernel<1><<<NTOK, 256>>>(x, lag + l * DMODEL, lab + l * DMODEL, nullptr, h0, h1, sh);
        tgemm_i8<0><<<dim3(DMODEL / 128, NTOK / 128), 256, I8_SMEM>>>(
            h0, h1, sh, wq0 + oQ, wq1 + oQ, swq + l * DMODEL, bq + l * DMODEL, q, DMODEL, DMODEL);
        tgemm_i8<0><<<dim3(KVW / 128, NTOK / 128), 256, I8_SMEM>>>(
            h0, h1, sh, wkv0 + oKV, wkv1 + oKV, swkv + l * KVW, bkv + l * KVW, kv, KVW, DMODEL);
        scores_kernel<<<dim3(SEQ / 64, SEQ / 64, BATCH * NHEAD), 256>>>(q, kv, sc);
        softmax_kernel<<<(BATCH * NHEAD * SEQ * 32) / 256, 256>>>(sc, lengths);
        av_kernel<<<dim3(1, SEQ / 64, BATCH * NHEAD), 256>>>(sc, kv, q);   // o into q (q consumed)
        quant_rows<<<NTOK, 256>>>(q, o0, o1, so, DMODEL);
        tgemm_i8<1><<<dim3(DMODEL / 128, NTOK / 128), 256, I8_SMEM>>>(
            o0, o1, so, wo0 + oQ, wo1 + oQ, swo + l * DMODEL, bo + l * DMODEL, x, DMODEL, DMODEL);

        // FFN sublayer
        ln_kernel<1><<<NTOK, 256>>>(x, lfg + l * DMODEL, lfb + l * DMODEL, nullptr, h0, h1, sh);
        tgemm_i8<2><<<dim3(DFF / 128, NTOK / 128), 256, I8_SMEM>>>(
            h0, h1, sh, w10 + o1w, w11 + o1w, sw1 + l * DFF, b1 + l * DFF, ffn, DFF, DMODEL);
        quant_rows<<<NTOK, 256>>>(ffn, f0, f1, sf, DFF);
        tgemm_i8<1><<<dim3(DMODEL / 128, NTOK / 128), 256, I8_SMEM>>>(
            f0, f1, sf, w20 + o1w, w21 + o1w, sw2 + l * DMODEL, b2 + l * DMODEL, x, DMODEL, DFF);
    }

    ln_kernel<0><<<NTOK, 256>>>(x, lng, lnb, (float*)d_out, nullptr, nullptr, nullptr);
}

// round 6
// speedup vs baseline: 2.7360x; 2.7360x over previous
#include <cuda_runtime.h>
#include <cuda_fp16.h>
#include <math.h>
#include <stdint.h>

// ---------------- problem dims ----------------
#define BATCH   8
#define SEQ     512
#define NTOK    4096
#define DMODEL  1024
#define NHEAD   16
#define DHEAD   64
#define DFF     4096
#define NLAYER  6
#define KVW     2048

typedef __half fp16;

// ---------------- scratch ----------------
__device__ float g_x  [(size_t)NTOK * DMODEL];
__device__ float g_q  [(size_t)NTOK * DMODEL];
__device__ float g_kv [(size_t)NTOK * KVW];
__device__ float g_sc [(size_t)BATCH * NHEAD * SEQ * SEQ];
__device__ float g_pe [(size_t)SEQ * DMODEL];

// activation splits (fp16 hi/lo)
__device__ fp16 g_hh[(size_t)NTOK * DMODEL];
__device__ fp16 g_hl[(size_t)NTOK * DMODEL];
__device__ fp16 g_oh[(size_t)NTOK * DMODEL];
__device__ fp16 g_ol[(size_t)NTOK * DMODEL];
__device__ fp16 g_fh[(size_t)NTOK * DFF];
__device__ fp16 g_fl[(size_t)NTOK * DFF];

// transposed weights: [N,K] fp16 single
__device__ fp16 g_wqT [(size_t)NLAYER * DMODEL * DMODEL];
__device__ fp16 g_wkvT[(size_t)NLAYER * DMODEL * KVW];
__device__ fp16 g_woT [(size_t)NLAYER * DMODEL * DMODEL];
__device__ fp16 g_w1T [(size_t)NLAYER * DMODEL * DFF];
__device__ fp16 g_w2T [(size_t)NLAYER * DFF * DMODEL];

// ---------------- helpers ----------------
__device__ __forceinline__ uint32_t smem_u32(const void* p) {
    uint32_t a;
    asm("{ .reg .u64 t; cvta.to.shared.u64 t, %1; cvt.u32.u64 %0, t; }" : "=r"(a) : "l"(p));
    return a;
}
#define CP_ASYNC16(dst, src) \
    asm volatile("cp.async.cg.shared.global [%0], [%1], 16;" :: "r"(dst), "l"(src) : "memory")
#define CP_COMMIT() asm volatile("cp.async.commit_group;" ::: "memory")
#define CP_WAIT2()  asm volatile("cp.async.wait_group 2;" ::: "memory")
#define CP_WAIT1()  asm volatile("cp.async.wait_group 1;" ::: "memory")
#define CP_WAIT0()  asm volatile("cp.async.wait_group 0;" ::: "memory")

__device__ __forceinline__ void ldsm4(uint32_t* r, uint32_t addr) {
    asm volatile("ldmatrix.sync.aligned.m8n8.x4.shared.b16 {%0,%1,%2,%3}, [%4];"
        : "=r"(r[0]), "=r"(r[1]), "=r"(r[2]), "=r"(r[3]) : "r"(addr));
}
__device__ __forceinline__ void mma_f16(float* d, const uint32_t* a, const uint32_t* b) {
    asm volatile("mma.sync.aligned.m16n8k16.row.col.f32.f16.f16.f32 "
        "{%0,%1,%2,%3}, {%4,%5,%6,%7}, {%8,%9}, {%0,%1,%2,%3};"
        : "+f"(d[0]), "+f"(d[1]), "+f"(d[2]), "+f"(d[3])
        : "r"(a[0]), "r"(a[1]), "r"(a[2]), "r"(a[3]), "r"(b[0]), "r"(b[1]));
}

// ---------------- fp16 2-pass GEMM: C[M,N] = (Ah+Al) @ Bt^T ----------------
// CTA 128x256, 8 warps (2x4), warp tile 64x64, BK=32, 3-stage cp.async.
// MODE 0: fp32+bias; 1: +residual; 2: relu -> fp16 hi/lo
#define ROWB   80
#define OFF_AH 0
#define OFF_AL 10240
#define OFF_B  20480
#define STAGE  40960
#define NSTAGE 3
#define SMEM_T (NSTAGE * STAGE)

template <int MODE>
__global__ void __launch_bounds__(256) tgemm(const fp16* __restrict__ Ah, const fp16* __restrict__ Al,
                                             const fp16* __restrict__ Bw,
                                             const float* __restrict__ bias,
                                             float* __restrict__ Cf,
                                             fp16* __restrict__ Ch, fp16* __restrict__ Cl,
                                             int N, int K) {
    extern __shared__ char smem[];
    const uint32_t sb = smem_u32(smem);
    const int tid  = threadIdx.x;
    const int wid  = tid >> 5, lane = tid & 31;
    const int wm   = wid >> 2, wn = wid & 3;       // warp grid 2 x 4, warp tile 64x64
    const int bm   = blockIdx.y << 7;
    const int bn   = blockIdx.x << 8;
    const int T    = K >> 5;

    float acc[4][8][4] = {};

    auto load_stage = [&](int sidx, int k0) {
        uint32_t stg = sb + sidx * STAGE;
#pragma unroll
        for (int i = 0; i < 4; i++) {
            int flat = tid + i * 256;           // 0..1023  A hi/lo (128 rows x 4 chunks x 2 planes)
            int half = flat >> 9;
            int idx  = flat & 511;
            int r = idx >> 2, c = idx & 3;
            const fp16* src = (half ? Al : Ah) + (size_t)(bm + r) * K + k0 + c * 8;
            CP_ASYNC16(stg + (half ? OFF_AL : OFF_AH) + r * ROWB + c * 16, src);
        }
#pragma unroll
        for (int i = 0; i < 4; i++) {
            int flat = tid + i * 256;           // 0..1023  B single (256 rows x 4 chunks)
            int r = flat >> 2, c = flat & 3;
            const fp16* src = Bw + (size_t)(bn + r) * K + k0 + c * 8;
            CP_ASYNC16(stg + OFF_B + r * ROWB + c * 16, src);
        }
        CP_COMMIT();
    };

    load_stage(0, 0);
    load_stage(1, 32);

    const int aRow  = lane & 15;
    const int aKc   = (lane >> 4) * 16;
    const int bNloc = ((lane >> 4) << 3) + (lane & 7);
    const int bKc   = ((lane >> 3) & 1) * 16;

    for (int it = 0; it < T; it++) {
        if (it + 2 < T) load_stage((it + 2) % NSTAGE, (it + 2) << 5);
        int remain = T - 1 - it;
        if (remain >= 2)      { CP_WAIT2(); }
        else if (remain == 1) { CP_WAIT1(); }
        else                  { CP_WAIT0(); }
        __syncthreads();

        uint32_t stg = sb + (it % NSTAGE) * STAGE;
        uint32_t aH = stg + OFF_AH + (wm * 64 + aRow) * ROWB + aKc;
        uint32_t aL = stg + OFF_AL + (wm * 64 + aRow) * ROWB + aKc;
        uint32_t bB = stg + OFF_B  + (wn * 64 + bNloc) * ROWB + bKc;

#pragma unroll
        for (int kk = 0; kk < 2; kk++) {
            uint32_t ka = kk * 32;
            uint32_t ah[4][4], al[4][4], bf[8][2];
#pragma unroll
            for (int mi = 0; mi < 4; mi++) {
                ldsm4(ah[mi], aH + mi * 16 * ROWB + ka);
                ldsm4(al[mi], aL + mi * 16 * ROWB + ka);
            }
#pragma unroll
            for (int ni2 = 0; ni2 < 4; ni2++) {
                uint32_t r[4];
                ldsm4(r, bB + ni2 * 16 * ROWB + ka);
                bf[ni2 * 2][0] = r[0]; bf[ni2 * 2][1] = r[1];
                bf[ni2 * 2 + 1][0] = r[2]; bf[ni2 * 2 + 1][1] = r[3];
            }
#pragma unroll
            for (int mi = 0; mi < 4; mi++)
#pragma unroll
                for (int ni = 0; ni < 8; ni++) {
                    mma_f16(acc[mi][ni], ah[mi], bf[ni]);
                    mma_f16(acc[mi][ni], al[mi], bf[ni]);
                }
        }
        __syncthreads();
    }

    // epilogue
#pragma unroll
    for (int mi = 0; mi < 4; mi++) {
        int row0 = bm + wm * 64 + mi * 16 + (lane >> 2);
#pragma unroll
        for (int ni = 0; ni < 8; ni++) {
            int col = bn + wn * 64 + ni * 8 + (lane & 3) * 2;
            float b0 = bias[col], b1 = bias[col + 1];
#pragma unroll
            for (int half = 0; half < 2; half++) {
                int row = row0 + half * 8;
                float v0 = acc[mi][ni][half * 2]     + b0;
                float v1 = acc[mi][ni][half * 2 + 1] + b1;
                if (MODE == 2) {
                    v0 = fmaxf(v0, 0.f); v1 = fmaxf(v1, 0.f);
                    fp16 h0 = __float2half_rn(v0), h1 = __float2half_rn(v1);
                    fp16 l0 = __float2half_rn(v0 - __half2float(h0));
                    fp16 l1 = __float2half_rn(v1 - __half2float(h1));
                    __half2 ph = __halves2half2(h0, h1);
                    __half2 pl = __halves2half2(l0, l1);
                    *(uint32_t*)(Ch + (size_t)row * N + col) = *(uint32_t*)&ph;
                    *(uint32_t*)(Cl + (size_t)row * N + col) = *(uint32_t*)&pl;
                } else {
                    float* dst = Cf + (size_t)row * N + col;
                    float v0r = v0, v1r = v1;
                    if (MODE == 1) { v0r += dst[0]; v1r += dst[1]; }
                    float2 o; o.x = v0r; o.y = v1r;
                    *(float2*)dst = o;
                }
            }
        }
    }
}

// ---------------- weight transpose to fp16: W[K,N] -> T[N,K] ----------------
__global__ void wsplit(const float* __restrict__ W, fp16* __restrict__ Tw, int K, int N) {
    __shared__ float t[32][33];
    const size_t lo = (size_t)blockIdx.z * K * N;
    const float* Wl = W + lo;
    fp16* tw = Tw + lo;
    int k0 = blockIdx.y << 5, n0 = blockIdx.x << 5;
    int tx = threadIdx.x, ty = threadIdx.y;
#pragma unroll
    for (int i = 0; i < 4; i++)
        t[ty + i * 8][tx] = Wl[(size_t)(k0 + ty + i * 8) * N + n0 + tx];
    __syncthreads();
#pragma unroll
    for (int i = 0; i < 4; i++) {
        size_t di = (size_t)(n0 + ty + i * 8) * K + k0 + tx;
        tw[di] = __float2half_rn(t[tx][ty + i * 8]);
    }
}

// ---------------- positional encoding ----------------
__global__ void pe_kernel(float* __restrict__ pe) {
    int idx = blockIdx.x * 256 + threadIdx.x;
    if (idx >= SEQ * DMODEL) return;
    int s = idx >> 10;
    int d = idx & 1023;
    double e = (double)(2 * (d >> 1)) / 1024.0;
    double ang = (double)s * exp(-e * log(10000.0));
    pe[idx] = (d & 1) ? (float)cos(ang) : (float)sin(ang);
}

// ---------------- embedding + PE ----------------
__global__ void embed_kernel(const int* __restrict__ tokens, const float* __restrict__ emb,
                             const float* __restrict__ pe, float* __restrict__ x) {
    int idx = blockIdx.x * 256 + threadIdx.x;
    if (idx >= NTOK * DMODEL) return;
    int row = idx >> 10;
    int d = idx & 1023;
    int s = row & (SEQ - 1);
    x[idx] = emb[(size_t)tokens[row] * DMODEL + d] * 32.0f + pe[(s << 10) + d];
}

// ---------------- layernorm (SPLIT=1 -> fp16 hi/lo out; 0 -> fp32 out) ----------------
template <int SPLIT>
__global__ void __launch_bounds__(256) ln_kernel(const float* __restrict__ in,
                                                 const float* __restrict__ g,
                                                 const float* __restrict__ b,
                                                 float* __restrict__ outf,
                                                 fp16* __restrict__ oh, fp16* __restrict__ ol) {
    int row = blockIdx.x;
    const float* xr = in + (size_t)row * DMODEL;
    float v[4];
    float s = 0.f, s2 = 0.f;
#pragma unroll
    for (int i = 0; i < 4; i++) {
        v[i] = xr[threadIdx.x + i * 256];
        s += v[i]; s2 += v[i] * v[i];
    }
    __shared__ float rs[8], rs2[8];
#pragma unroll
    for (int off = 16; off; off >>= 1) {
        s  += __shfl_xor_sync(0xffffffffu, s, off);
        s2 += __shfl_xor_sync(0xffffffffu, s2, off);
    }
    if ((threadIdx.x & 31) == 0) { rs[threadIdx.x >> 5] = s; rs2[threadIdx.x >> 5] = s2; }
    __syncthreads();
    if (threadIdx.x < 32) {
        s  = (threadIdx.x < 8) ? rs[threadIdx.x] : 0.f;
        s2 = (threadIdx.x < 8) ? rs2[threadIdx.x] : 0.f;
#pragma unroll
        for (int off = 4; off; off >>= 1) {
            s  += __shfl_xor_sync(0xffffffffu, s, off);
            s2 += __shfl_xor_sync(0xffffffffu, s2, off);
        }
        if (threadIdx.x == 0) { rs[0] = s; rs2[0] = s2; }
    }
    __syncthreads();
    float m = rs[0] * (1.f / DMODEL);
    float var = rs2[0] * (1.f / DMODEL) - m * m;
    float rstd = rsqrtf(var + 1e-5f);
#pragma unroll
    for (int i = 0; i < 4; i++) {
        int c = threadIdx.x + i * 256;
        float val = (v[i] - m) * rstd * g[c] + b[c];
        if (SPLIT) {
            fp16 h = __float2half_rn(val);
            oh[(size_t)row * DMODEL + c] = h;
            ol[(size_t)row * DMODEL + c] = __float2half_rn(val - __half2float(h));
        } else {
            outf[(size_t)row * DMODEL + c] = val;
        }
    }
}

// ---------------- scores ----------------
__global__ void __launch_bounds__(256) scores_kernel(const float* __restrict__ q,
                                                     const float* __restrict__ kv,
                                                     float* __restrict__ sc) {
    int bh = blockIdx.z;
    int b = bh >> 4, h = bh & 15;
    int qi0 = blockIdx.y << 6, ki0 = blockIdx.x << 6;
    __shared__ float Qs[16][68], Ks[16][68];
    int tid = threadIdx.x;
    int tx = tid & 15, ty = tid >> 4;
    float acc[4][4] = {};
    const float* qbase = q  + ((size_t)(b * SEQ) + qi0) * DMODEL + h * DHEAD;
    const float* kbase = kv + ((size_t)(b * SEQ) + ki0) * KVW + h * DHEAD;
    int lr = tid >> 2, lc = (tid & 3) << 2;
    for (int d0 = 0; d0 < DHEAD; d0 += 16) {
        float4 qv = *(const float4*)(qbase + (size_t)lr * DMODEL + d0 + lc);
        Qs[lc + 0][lr] = qv.x; Qs[lc + 1][lr] = qv.y; Qs[lc + 2][lr] = qv.z; Qs[lc + 3][lr] = qv.w;
        float4 kk = *(const float4*)(kbase + (size_t)lr * KVW + d0 + lc);
        Ks[lc + 0][lr] = kk.x; Ks[lc + 1][lr] = kk.y; Ks[lc + 2][lr] = kk.z; Ks[lc + 3][lr] = kk.w;
        __syncthreads();
#pragma unroll
        for (int k = 0; k < 16; k++) {
            float ra[4], rb[4];
#pragma unroll
            for (int i = 0; i < 4; i++) ra[i] = Qs[k][ty * 4 + i];
#pragma unroll
            for (int j = 0; j < 4; j++) rb[j] = Ks[k][tx * 4 + j];
#pragma unroll
            for (int i = 0; i < 4; i++)
#pragma unroll
                for (int j = 0; j < 4; j++)
                    acc[i][j] = fmaf(ra[i], rb[j], acc[i][j]);
        }
        __syncthreads();
    }
#pragma unroll
    for (int i = 0; i < 4; i++) {
        float* srow = sc + ((size_t)bh * SEQ + qi0 + ty * 4 + i) * SEQ + ki0 + tx * 4;
        *(float4*)srow = make_float4(acc[i][0] * 0.125f, acc[i][1] * 0.125f,
                                     acc[i][2] * 0.125f, acc[i][3] * 0.125f);
    }
}

// ---------------- masked softmax ----------------
__global__ void __launch_bounds__(256) softmax_kernel(float* __restrict__ sc,
                                                      const int* __restrict__ lengths) {
    int gw = (blockIdx.x * blockDim.x + threadIdx.x) >> 5;
    int lane = threadIdx.x & 31;
    if (gw >= BATCH * NHEAD * SEQ) return;
    int b = gw >> 13;
    int len = lengths[b];
    float* row = sc + (size_t)gw * SEQ;
    float v[16];
    float mx = -1e30f;
#pragma unroll
    for (int i = 0; i < 16; i++) {
        int c = lane + i * 32;
        v[i] = (c < len) ? row[c] : -1e30f;
        mx = fmaxf(mx, v[i]);
    }
#pragma unroll
    for (int off = 16; off; off >>= 1) mx = fmaxf(mx, __shfl_xor_sync(0xffffffffu, mx, off));
    float s = 0.f;
#pragma unroll
    for (int i = 0; i < 16; i++) {
        int c = lane + i * 32;
        v[i] = (c < len) ? __expf(v[i] - mx) : 0.f;
        s += v[i];
    }
#pragma unroll
    for (int off = 16; off; off >>= 1) s += __shfl_xor_sync(0xffffffffu, s, off);
    float inv = 1.f / s;
#pragma unroll
    for (int i = 0; i < 16; i++) row[lane + i * 32] = v[i] * inv;
}

// ---------------- AV -> fp16 hi/lo ----------------
__global__ void __launch_bounds__(256) av_kernel(const float* __restrict__ sc,
                                                 const float* __restrict__ kv,
                                                 fp16* __restrict__ oh, fp16* __restrict__ ol) {
    int bh = blockIdx.z;
    int b = bh >> 4, h = bh & 15;
    int qi0 = blockIdx.y << 6;
    __shared__ float Ps[16][68], Vs[16][68];
    int tid = threadIdx.x;
    int tx = tid & 15, ty = tid >> 4;
    float acc[4][4] = {};
    const float* prow = sc + ((size_t)bh * SEQ + qi0) * SEQ;
    const float* vbase = kv + (size_t)b * SEQ * KVW + NHEAD * DHEAD + h * DHEAD;
    int lr = tid >> 2, lc = (tid & 3) << 2;
    int vr = tid >> 4, vc = (tid & 15) << 2;
    for (int k0 = 0; k0 < SEQ; k0 += 16) {
        float4 pv = *(const float4*)(prow + (size_t)lr * SEQ + k0 + lc);
        Ps[lc + 0][lr] = pv.x; Ps[lc + 1][lr] = pv.y; Ps[lc + 2][lr] = pv.z; Ps[lc + 3][lr] = pv.w;
        *(float4*)&Vs[vr][vc] = *(const float4*)(vbase + (size_t)(k0 + vr) * KVW + vc);
        __syncthreads();
#pragma unroll
        for (int k = 0; k < 16; k++) {
            float ra[4], rb[4];
#pragma unroll
            for (int i = 0; i < 4; i++) ra[i] = Ps[k][ty * 4 + i];
#pragma unroll
            for (int j = 0; j < 4; j++) rb[j] = Vs[k][tx * 4 + j];
#pragma unroll
            for (int i = 0; i < 4; i++)
#pragma unroll
                for (int j = 0; j < 4; j++)
                    acc[i][j] = fmaf(ra[i], rb[j], acc[i][j]);
        }
        __syncthreads();
    }
#pragma unroll
    for (int i = 0; i < 4; i++) {
        size_t base = ((size_t)(b * SEQ) + qi0 + ty * 4 + i) * DMODEL + h * DHEAD + tx * 4;
#pragma unroll
        for (int j = 0; j < 4; j++) {
            float v = acc[i][j];
            fp16 hh = __float2half_rn(v);
            oh[base + j] = hh;
            ol[base + j] = __float2half_rn(v - __half2float(hh));
        }
    }
}

// ---------------- host ----------------
extern "C" void kernel_launch(void* const* d_in, const int* in_sizes, int n_in,
                              void* d_out, int out_size) {
    const int*   tokens = (const int*)  d_in[0];
    const int*   lengths= (const int*)  d_in[1];
    const float* emb    = (const float*)d_in[2];
    const float* Wq     = (const float*)d_in[3];
    const float* bq     = (const float*)d_in[4];
    const float* Wkv    = (const float*)d_in[5];
    const float* bkv    = (const float*)d_in[6];
    const float* Wo     = (const float*)d_in[7];
    const float* bo     = (const float*)d_in[8];
    const float* lag    = (const float*)d_in[9];
    const float* lab    = (const float*)d_in[10];
    const float* W1     = (const float*)d_in[11];
    const float* b1     = (const float*)d_in[12];
    const float* W2     = (const float*)d_in[13];
    const float* b2     = (const float*)d_in[14];
    const float* lfg    = (const float*)d_in[15];
    const float* lfb    = (const float*)d_in[16];
    const float* lng    = (const float*)d_in[17];
    const float* lnb    = (const float*)d_in[18];

    float *x, *q, *kv, *sc, *pe;
    fp16 *hh, *hl, *oh, *ol, *fh, *fl;
    fp16 *wqT, *wkvT, *woT, *w1T, *w2T;
    cudaGetSymbolAddress((void**)&x, g_x);
    cudaGetSymbolAddress((void**)&q, g_q);
    cudaGetSymbolAddress((void**)&kv, g_kv);
    cudaGetSymbolAddress((void**)&sc, g_sc);
    cudaGetSymbolAddress((void**)&pe, g_pe);
    cudaGetSymbolAddress((void**)&hh, g_hh);
    cudaGetSymbolAddress((void**)&hl, g_hl);
    cudaGetSymbolAddress((void**)&oh, g_oh);
    cudaGetSymbolAddress((void**)&ol, g_ol);
    cudaGetSymbolAddress((void**)&fh, g_fh);
    cudaGetSymbolAddress((void**)&fl, g_fl);
    cudaGetSymbolAddress((void**)&wqT, g_wqT);
    cudaGetSymbolAddress((void**)&wkvT, g_wkvT);
    cudaGetSymbolAddress((void**)&woT, g_woT);
    cudaGetSymbolAddress((void**)&w1T, g_w1T);
    cudaGetSymbolAddress((void**)&w2T, g_w2T);

    cudaFuncSetAttribute(tgemm<0>, cudaFuncAttributeMaxDynamicSharedMemorySize, SMEM_T);
    cudaFuncSetAttribute(tgemm<1>, cudaFuncAttributeMaxDynamicSharedMemorySize, SMEM_T);
    cudaFuncSetAttribute(tgemm<2>, cudaFuncAttributeMaxDynamicSharedMemorySize, SMEM_T);

    dim3 tb(32, 8);
    wsplit<<<dim3(DMODEL / 32, DMODEL / 32, NLAYER), tb>>>(Wq,  wqT,  DMODEL, DMODEL);
    wsplit<<<dim3(KVW / 32,    DMODEL / 32, NLAYER), tb>>>(Wkv, wkvT, DMODEL, KVW);
    wsplit<<<dim3(DMODEL / 32, DMODEL / 32, NLAYER), tb>>>(Wo,  woT,  DMODEL, DMODEL);
    wsplit<<<dim3(DFF / 32,    DMODEL / 32, NLAYER), tb>>>(W1,  w1T,  DMODEL, DFF);
    wsplit<<<dim3(DMODEL / 32, DFF / 32,    NLAYER), tb>>>(W2,  w2T,  DFF,    DMODEL);

    pe_kernel<<<(SEQ * DMODEL) / 256, 256>>>(pe);
    embed_kernel<<<(NTOK * DMODEL) / 256, 256>>>(tokens, emb, pe, x);

    for (int l = 0; l < NLAYER; l++) {
        size_t oQ  = (size_t)l * DMODEL * DMODEL;
        size_t oKV = (size_t)l * DMODEL * KVW;
        size_t o1w = (size_t)l * DMODEL * DFF;

        // attention sublayer
        ln_kernel<1><<<NTOK, 256>>>(x, lag + l * DMODEL, lab + l * DMODEL, nullptr, hh, hl);
        tgemm<0><<<dim3(DMODEL / 256, NTOK / 128), 256, SMEM_T>>>(
            hh, hl, wqT + oQ, bq + l * DMODEL, q, nullptr, nullptr, DMODEL, DMODEL);
        tgemm<0><<<dim3(KVW / 256, NTOK / 128), 256, SMEM_T>>>(
            hh, hl, wkvT + oKV, bkv + l * KVW, kv, nullptr, nullptr, KVW, DMODEL);
        scores_kernel<<<dim3(SEQ / 64, SEQ / 64, BATCH * NHEAD), 256>>>(q, kv, sc);
        softmax_kernel<<<(BATCH * NHEAD * SEQ * 32) / 256, 256>>>(sc, lengths);
        av_kernel<<<dim3(1, SEQ / 64, BATCH * NHEAD), 256>>>(sc, kv, oh, ol);
        tgemm<1><<<dim3(DMODEL / 256, NTOK / 128), 256, SMEM_T>>>(
            oh, ol, woT + oQ, bo + l * DMODEL, x, nullptr, nullptr, DMODEL, DMODEL);

        // FFN sublayer
        ln_kernel<1><<<NTOK, 256>>>(x, lfg + l * DMODEL, lfb + l * DMODEL, nullptr, hh, hl);
        tgemm<2><<<dim3(DFF / 256, NTOK / 128), 256, SMEM_T>>>(
            hh, hl, w1T + o1w, b1 + l * DFF, nullptr, fh, fl, DFF, DMODEL);
        tgemm<1><<<dim3(DMODEL / 256, NTOK / 128), 256, SMEM_T>>>(
            fh, fl, w2T + o1w, b2 + l * DMODEL, x, nullptr, nullptr, DMODEL, DFF);
    }

    ln_kernel<0><<<NTOK, 256>>>(x, lng, lnb, (float*)d_out, nullptr, nullptr);
}

// round 7
// speedup vs baseline: 3.4624x; 1.2655x over previous
#include <cuda_runtime.h>
#include <cuda_fp16.h>
#include <math.h>
#include <stdint.h>

// ---------------- problem dims ----------------
#define BATCH   8
#define SEQ     512
#define NTOK    4096
#define DMODEL  1024
#define NHEAD   16
#define DHEAD   64
#define DFF     4096
#define NLAYER  6
#define KVW     2048

typedef __half fp16;

// ---------------- scratch ----------------
__device__ float g_x [(size_t)NTOK * DMODEL];
__device__ float g_pe[(size_t)SEQ * DMODEL];

__device__ fp16 g_q16 [(size_t)NTOK * DMODEL];
__device__ fp16 g_kv16[(size_t)NTOK * KVW];

// activation splits (fp16 hi/lo)
__device__ fp16 g_hh[(size_t)NTOK * DMODEL];
__device__ fp16 g_hl[(size_t)NTOK * DMODEL];
__device__ fp16 g_oh[(size_t)NTOK * DMODEL];
__device__ fp16 g_ol[(size_t)NTOK * DMODEL];
__device__ fp16 g_fh[(size_t)NTOK * DFF];
__device__ fp16 g_fl[(size_t)NTOK * DFF];

// transposed weights: [N,K] fp16
__device__ fp16 g_wqT [(size_t)NLAYER * DMODEL * DMODEL];
__device__ fp16 g_wkvT[(size_t)NLAYER * DMODEL * KVW];
__device__ fp16 g_woT [(size_t)NLAYER * DMODEL * DMODEL];
__device__ fp16 g_w1T [(size_t)NLAYER * DMODEL * DFF];
__device__ fp16 g_w2T [(size_t)NLAYER * DFF * DMODEL];

// ---------------- helpers ----------------
__device__ __forceinline__ uint32_t smem_u32(const void* p) {
    uint32_t a;
    asm("{ .reg .u64 t; cvta.to.shared.u64 t, %1; cvt.u32.u64 %0, t; }" : "=r"(a) : "l"(p));
    return a;
}
#define CP_ASYNC16(dst, src) \
    asm volatile("cp.async.cg.shared.global [%0], [%1], 16;" :: "r"(dst), "l"(src) : "memory")
#define CP_COMMIT() asm volatile("cp.async.commit_group;" ::: "memory")
#define CP_WAIT2()  asm volatile("cp.async.wait_group 2;" ::: "memory")
#define CP_WAIT1()  asm volatile("cp.async.wait_group 1;" ::: "memory")
#define CP_WAIT0()  asm volatile("cp.async.wait_group 0;" ::: "memory")

__device__ __forceinline__ void ldsm4(uint32_t* r, uint32_t addr) {
    asm volatile("ldmatrix.sync.aligned.m8n8.x4.shared.b16 {%0,%1,%2,%3}, [%4];"
        : "=r"(r[0]), "=r"(r[1]), "=r"(r[2]), "=r"(r[3]) : "r"(addr));
}
__device__ __forceinline__ void mma_f16(float* d, const uint32_t* a, const uint32_t* b) {
    asm volatile("mma.sync.aligned.m16n8k16.row.col.f32.f16.f16.f32 "
        "{%0,%1,%2,%3}, {%4,%5,%6,%7}, {%8,%9}, {%0,%1,%2,%3};"
        : "+f"(d[0]), "+f"(d[1]), "+f"(d[2]), "+f"(d[3])
        : "r"(a[0]), "r"(a[1]), "r"(a[2]), "r"(a[3]), "r"(b[0]), "r"(b[1]));
}
__device__ __forceinline__ uint32_t pack_h2(float a, float b) {
    __half2 h = __halves2half2(__float2half_rn(a), __float2half_rn(b));
    return *(uint32_t*)&h;
}

// ---------------- fp16 2-pass GEMM: C[M,N] = (Ah+Al) @ Bt^T ----------------
// CTA 128x256, 8 warps (2x4), warp tile 64x64, BK=32, 3-stage cp.async.
// MODE 0: fp32+bias; 1: +residual; 2: relu -> fp16 hi/lo; 3: fp16 single
#define ROWB   80
#define OFF_AH 0
#define OFF_AL 10240
#define OFF_B  20480
#define STAGE  40960
#define NSTAGE 3
#define SMEM_T (NSTAGE * STAGE)

template <int MODE>
__global__ void __launch_bounds__(256) tgemm(const fp16* __restrict__ Ah, const fp16* __restrict__ Al,
                                             const fp16* __restrict__ Bw,
                                             const float* __restrict__ bias,
                                             float* __restrict__ Cf,
                                             fp16* __restrict__ Ch, fp16* __restrict__ Cl,
                                             int N, int K) {
    extern __shared__ char smem[];
    const uint32_t sb = smem_u32(smem);
    const int tid  = threadIdx.x;
    const int wid  = tid >> 5, lane = tid & 31;
    const int wm   = wid >> 2, wn = wid & 3;
    const int bm   = blockIdx.y << 7;
    const int bn   = blockIdx.x << 8;
    const int T    = K >> 5;

    float acc[4][8][4] = {};

    auto load_stage = [&](int sidx, int k0) {
        uint32_t stg = sb + sidx * STAGE;
#pragma unroll
        for (int i = 0; i < 4; i++) {
            int flat = tid + i * 256;
            int half = flat >> 9;
            int idx  = flat & 511;
            int r = idx >> 2, c = idx & 3;
            const fp16* src = (half ? Al : Ah) + (size_t)(bm + r) * K + k0 + c * 8;
            CP_ASYNC16(stg + (half ? OFF_AL : OFF_AH) + r * ROWB + c * 16, src);
        }
#pragma unroll
        for (int i = 0; i < 4; i++) {
            int flat = tid + i * 256;
            int r = flat >> 2, c = flat & 3;
            const fp16* src = Bw + (size_t)(bn + r) * K + k0 + c * 8;
            CP_ASYNC16(stg + OFF_B + r * ROWB + c * 16, src);
        }
        CP_COMMIT();
    };

    load_stage(0, 0);
    load_stage(1, 32);

    const int aRow  = lane & 15;
    const int aKc   = (lane >> 4) * 16;
    const int bNloc = ((lane >> 4) << 3) + (lane & 7);
    const int bKc   = ((lane >> 3) & 1) * 16;

    for (int it = 0; it < T; it++) {
        if (it + 2 < T) load_stage((it + 2) % NSTAGE, (it + 2) << 5);
        int remain = T - 1 - it;
        if (remain >= 2)      { CP_WAIT2(); }
        else if (remain == 1) { CP_WAIT1(); }
        else                  { CP_WAIT0(); }
        __syncthreads();

        uint32_t stg = sb + (it % NSTAGE) * STAGE;
        uint32_t aH = stg + OFF_AH + (wm * 64 + aRow) * ROWB + aKc;
        uint32_t aL = stg + OFF_AL + (wm * 64 + aRow) * ROWB + aKc;
        uint32_t bB = stg + OFF_B  + (wn * 64 + bNloc) * ROWB + bKc;

#pragma unroll
        for (int kk = 0; kk < 2; kk++) {
            uint32_t ka = kk * 32;
            uint32_t ah[4][4], al[4][4], bf[8][2];
#pragma unroll
            for (int mi = 0; mi < 4; mi++) {
                ldsm4(ah[mi], aH + mi * 16 * ROWB + ka);
                ldsm4(al[mi], aL + mi * 16 * ROWB + ka);
            }
#pragma unroll
            for (int ni2 = 0; ni2 < 4; ni2++) {
                uint32_t r[4];
                ldsm4(r, bB + ni2 * 16 * ROWB + ka);
                bf[ni2 * 2][0] = r[0]; bf[ni2 * 2][1] = r[1];
                bf[ni2 * 2 + 1][0] = r[2]; bf[ni2 * 2 + 1][1] = r[3];
            }
#pragma unroll
            for (int mi = 0; mi < 4; mi++)
#pragma unroll
                for (int ni = 0; ni < 8; ni++) {
                    mma_f16(acc[mi][ni], ah[mi], bf[ni]);
                    mma_f16(acc[mi][ni], al[mi], bf[ni]);
                }
        }
        __syncthreads();
    }

#pragma unroll
    for (int mi = 0; mi < 4; mi++) {
        int row0 = bm + wm * 64 + mi * 16 + (lane >> 2);
#pragma unroll
        for (int ni = 0; ni < 8; ni++) {
            int col = bn + wn * 64 + ni * 8 + (lane & 3) * 2;
            float b0 = bias[col], b1 = bias[col + 1];
#pragma unroll
            for (int half = 0; half < 2; half++) {
                int row = row0 + half * 8;
                float v0 = acc[mi][ni][half * 2]     + b0;
                float v1 = acc[mi][ni][half * 2 + 1] + b1;
                if (MODE == 2) {
                    v0 = fmaxf(v0, 0.f); v1 = fmaxf(v1, 0.f);
                    fp16 h0 = __float2half_rn(v0), h1 = __float2half_rn(v1);
                    fp16 l0 = __float2half_rn(v0 - __half2float(h0));
                    fp16 l1 = __float2half_rn(v1 - __half2float(h1));
                    __half2 ph = __halves2half2(h0, h1);
                    __half2 pl = __halves2half2(l0, l1);
                    *(uint32_t*)(Ch + (size_t)row * N + col) = *(uint32_t*)&ph;
                    *(uint32_t*)(Cl + (size_t)row * N + col) = *(uint32_t*)&pl;
                } else if (MODE == 3) {
                    __half2 ph = __halves2half2(__float2half_rn(v0), __float2half_rn(v1));
                    *(uint32_t*)(Ch + (size_t)row * N + col) = *(uint32_t*)&ph;
                } else {
                    float* dst = Cf + (size_t)row * N + col;
                    float v0r = v0, v1r = v1;
                    if (MODE == 1) { v0r += dst[0]; v1r += dst[1]; }
                    float2 o; o.x = v0r; o.y = v1r;
                    *(float2*)dst = o;
                }
            }
        }
    }
}

// ---------------- fused flash attention ----------------
// grid (SEQ/128, BATCH*NHEAD), 256 threads (8 warps x 16 q-rows)
#define FA_ROWB   144
#define FA_VTROWB 272
#define FA_Q   0
#define FA_K0  18432
#define FA_K1  36864
#define FA_V0  55296
#define FA_V1  73728
#define FA_VT  92160
#define FA_SMEM 109568

__global__ void __launch_bounds__(256) fattn(const fp16* __restrict__ Qf, const fp16* __restrict__ KVf,
                                             const int* __restrict__ lengths,
                                             fp16* __restrict__ oh, fp16* __restrict__ ol) {
    extern __shared__ char smem[];
    const uint32_t sb = smem_u32(smem);
    const int tid = threadIdx.x, w = tid >> 5, lane = tid & 31;
    const int qb = blockIdx.x, bh = blockIdx.y;
    const int b = bh >> 4, h = bh & 15;
    const int len = lengths[b];
    const int tok0 = b * SEQ + qb * 128;

    // prologue: Q + K0/V0 (group0), K1/V1 (group1)
#pragma unroll
    for (int i = 0; i < 4; i++) {
        int flat = tid + i * 256; int r = flat >> 3, c = flat & 7;
        CP_ASYNC16(sb + FA_Q + r * FA_ROWB + c * 16, Qf + (size_t)(tok0 + r) * DMODEL + h * 64 + c * 8);
        CP_ASYNC16(sb + FA_K0 + r * FA_ROWB + c * 16, KVf + (size_t)(b * SEQ + r) * KVW + h * 64 + c * 8);
        CP_ASYNC16(sb + FA_V0 + r * FA_ROWB + c * 16, KVf + (size_t)(b * SEQ + r) * KVW + 1024 + h * 64 + c * 8);
    }
    CP_COMMIT();
#pragma unroll
    for (int i = 0; i < 4; i++) {
        int flat = tid + i * 256; int r = flat >> 3, c = flat & 7;
        CP_ASYNC16(sb + FA_K1 + r * FA_ROWB + c * 16, KVf + (size_t)(b * SEQ + 128 + r) * KVW + h * 64 + c * 8);
        CP_ASYNC16(sb + FA_V1 + r * FA_ROWB + c * 16, KVf + (size_t)(b * SEQ + 128 + r) * KVW + 1024 + h * 64 + c * 8);
    }
    CP_COMMIT();

    const int bNloc = ((lane >> 4) << 3) + (lane & 7);
    const int bKc   = ((lane >> 3) & 1) * 16;

    uint32_t qf[4][4];
    float O[8][4] = {};
    float m0 = -1e30f, m1 = -1e30f, l0 = 0.f, l1 = 0.f;

    for (int kb = 0; kb < 4; kb++) {
        if (kb < 3) { CP_WAIT1(); } else { CP_WAIT0(); }
        __syncthreads();

        if (kb == 0) {
            uint32_t qa = sb + FA_Q + (w * 16 + (lane & 15)) * FA_ROWB + (lane >> 4) * 16;
#pragma unroll
            for (int kc = 0; kc < 4; kc++) ldsm4(qf[kc], qa + kc * 32);
        }

        // transpose V(kb) -> VT [d][kpos]
        {
            const char* vsrcp = smem + ((kb & 1) ? FA_V1 : FA_V0);
            for (int idx = tid; idx < 4096; idx += 256) {
                int r = idx >> 5;
                int d2 = (idx & 31) << 1;
                __half2 vv = *reinterpret_cast<const __half2*>(vsrcp + r * FA_ROWB + d2 * 2);
                *reinterpret_cast<fp16*>(smem + FA_VT + (d2)     * FA_VTROWB + r * 2) = __low2half(vv);
                *reinterpret_cast<fp16*>(smem + FA_VT + (d2 + 1) * FA_VTROWB + r * 2) = __high2half(vv);
            }
        }
        __syncthreads();

        // ---- QK^T: p[16 n-tiles][4] ----
        uint32_t koff = sb + ((kb & 1) ? FA_K1 : FA_K0);
        float p[16][4];
#pragma unroll
        for (int nt16 = 0; nt16 < 8; nt16++) {
            float s0[4] = {}, s1[4] = {};
#pragma unroll
            for (int kc = 0; kc < 4; kc++) {
                uint32_t r4[4];
                ldsm4(r4, koff + (nt16 * 16 + bNloc) * FA_ROWB + bKc + kc * 32);
                uint32_t bb0[2] = { r4[0], r4[1] }, bb1[2] = { r4[2], r4[3] };
                mma_f16(s0, qf[kc], bb0);
                mma_f16(s1, qf[kc], bb1);
            }
#pragma unroll
            for (int j = 0; j < 4; j++) { p[nt16 * 2][j] = s0[j]; p[nt16 * 2 + 1][j] = s1[j]; }
        }

        // ---- mask + online softmax ----
        float mx0 = -1e30f, mx1 = -1e30f;
#pragma unroll
        for (int nt = 0; nt < 16; nt++) {
            int c = kb * 128 + nt * 8 + (lane & 3) * 2;
            float s0 = p[nt][0] * 0.125f, s1 = p[nt][1] * 0.125f;
            float s2 = p[nt][2] * 0.125f, s3 = p[nt][3] * 0.125f;
            if (c     >= len) { s0 = -1e30f; s2 = -1e30f; }
            if (c + 1 >= len) { s1 = -1e30f; s3 = -1e30f; }
            p[nt][0] = s0; p[nt][1] = s1; p[nt][2] = s2; p[nt][3] = s3;
            mx0 = fmaxf(mx0, fmaxf(s0, s1));
            mx1 = fmaxf(mx1, fmaxf(s2, s3));
        }
        mx0 = fmaxf(mx0, __shfl_xor_sync(0xffffffffu, mx0, 1));
        mx0 = fmaxf(mx0, __shfl_xor_sync(0xffffffffu, mx0, 2));
        mx1 = fmaxf(mx1, __shfl_xor_sync(0xffffffffu, mx1, 1));
        mx1 = fmaxf(mx1, __shfl_xor_sync(0xffffffffu, mx1, 2));
        float mn0 = fmaxf(m0, mx0), mn1 = fmaxf(m1, mx1);
        float corr0 = __expf(m0 - mn0), corr1 = __expf(m1 - mn1);
        m0 = mn0; m1 = mn1;
        float ls0 = 0.f, ls1 = 0.f;
#pragma unroll
        for (int nt = 0; nt < 16; nt++) {
            float e0 = __expf(p[nt][0] - mn0), e1 = __expf(p[nt][1] - mn0);
            float e2 = __expf(p[nt][2] - mn1), e3 = __expf(p[nt][3] - mn1);
            p[nt][0] = e0; p[nt][1] = e1; p[nt][2] = e2; p[nt][3] = e3;
            ls0 += e0 + e1; ls1 += e2 + e3;
        }
        l0 = l0 * corr0 + ls0;
        l1 = l1 * corr1 + ls1;
#pragma unroll
        for (int ni = 0; ni < 8; ni++) {
            O[ni][0] *= corr0; O[ni][1] *= corr0;
            O[ni][2] *= corr1; O[ni][3] *= corr1;
        }

        // ---- P @ V ----
#pragma unroll
        for (int kc = 0; kc < 8; kc++) {
            uint32_t pf[4];
            pf[0] = pack_h2(p[2 * kc][0],     p[2 * kc][1]);
            pf[1] = pack_h2(p[2 * kc][2],     p[2 * kc][3]);
            pf[2] = pack_h2(p[2 * kc + 1][0], p[2 * kc + 1][1]);
            pf[3] = pack_h2(p[2 * kc + 1][2], p[2 * kc + 1][3]);
#pragma unroll
            for (int nt16 = 0; nt16 < 4; nt16++) {
                uint32_t r4[4];
                ldsm4(r4, sb + FA_VT + (nt16 * 16 + bNloc) * FA_VTROWB + bKc + kc * 32);
                uint32_t bb0[2] = { r4[0], r4[1] }, bb1[2] = { r4[2], r4[3] };
                mma_f16(O[nt16 * 2], pf, bb0);
                mma_f16(O[nt16 * 2 + 1], pf, bb1);
            }
        }

        __syncthreads();
        if (kb < 2) {
            int blk = kb + 2;
            uint32_t kd = sb + ((blk & 1) ? FA_K1 : FA_K0);
            uint32_t vd = sb + ((blk & 1) ? FA_V1 : FA_V0);
#pragma unroll
            for (int i = 0; i < 4; i++) {
                int flat = tid + i * 256; int r = flat >> 3, c = flat & 7;
                CP_ASYNC16(kd + r * FA_ROWB + c * 16, KVf + (size_t)(b * SEQ + blk * 128 + r) * KVW + h * 64 + c * 8);
                CP_ASYNC16(vd + r * FA_ROWB + c * 16, KVf + (size_t)(b * SEQ + blk * 128 + r) * KVW + 1024 + h * 64 + c * 8);
            }
            CP_COMMIT();
        }
    }

    // final normalize + write fp16 hi/lo
    l0 += __shfl_xor_sync(0xffffffffu, l0, 1);
    l0 += __shfl_xor_sync(0xffffffffu, l0, 2);
    l1 += __shfl_xor_sync(0xffffffffu, l1, 1);
    l1 += __shfl_xor_sync(0xffffffffu, l1, 2);
    float inv0 = 1.f / l0, inv1 = 1.f / l1;
    int row0 = tok0 + w * 16 + (lane >> 2);
    int row1 = row0 + 8;
#pragma unroll
    for (int nt = 0; nt < 8; nt++) {
        int col = h * 64 + nt * 8 + (lane & 3) * 2;
        float v0 = O[nt][0] * inv0, v1 = O[nt][1] * inv0;
        float v2 = O[nt][2] * inv1, v3 = O[nt][3] * inv1;
        fp16 h0 = __float2half_rn(v0), h1 = __float2half_rn(v1);
        fp16 h2v = __float2half_rn(v2), h3 = __float2half_rn(v3);
        __half2 ph0 = __halves2half2(h0, h1);
        __half2 pl0 = __halves2half2(__float2half_rn(v0 - __half2float(h0)), __float2half_rn(v1 - __half2float(h1)));
        __half2 ph1 = __halves2half2(h2v, h3);
        __half2 pl1 = __halves2half2(__float2half_rn(v2 - __half2float(h2v)), __float2half_rn(v3 - __half2float(h3)));
        *(uint32_t*)(oh + (size_t)row0 * DMODEL + col) = *(uint32_t*)&ph0;
        *(uint32_t*)(ol + (size_t)row0 * DMODEL + col) = *(uint32_t*)&pl0;
        *(uint32_t*)(oh + (size_t)row1 * DMODEL + col) = *(uint32_t*)&ph1;
        *(uint32_t*)(ol + (size_t)row1 * DMODEL + col) = *(uint32_t*)&pl1;
    }
}

// ---------------- weight transpose to fp16 ----------------
__global__ void wsplit(const float* __restrict__ W, fp16* __restrict__ Tw, int K, int N) {
    __shared__ float t[32][33];
    const size_t lo = (size_t)blockIdx.z * K * N;
    const float* Wl = W + lo;
    fp16* tw = Tw + lo;
    int k0 = blockIdx.y << 5, n0 = blockIdx.x << 5;
    int tx = threadIdx.x, ty = threadIdx.y;
#pragma unroll
    for (int i = 0; i < 4; i++)
        t[ty + i * 8][tx] = Wl[(size_t)(k0 + ty + i * 8) * N + n0 + tx];
    __syncthreads();
#pragma unroll
    for (int i = 0; i < 4; i++) {
        size_t di = (size_t)(n0 + ty + i * 8) * K + k0 + tx;
        tw[di] = __float2half_rn(t[tx][ty + i * 8]);
    }
}

// ---------------- positional encoding ----------------
__global__ void pe_kernel(float* __restrict__ pe) {
    int idx = blockIdx.x * 256 + threadIdx.x;
    if (idx >= SEQ * DMODEL) return;
    int s = idx >> 10;
    int d = idx & 1023;
    double e = (double)(2 * (d >> 1)) / 1024.0;
    double ang = (double)s * exp(-e * log(10000.0));
    pe[idx] = (d & 1) ? (float)cos(ang) : (float)sin(ang);
}

// ---------------- embedding + PE ----------------
__global__ void embed_kernel(const int* __restrict__ tokens, const float* __restrict__ emb,
                             const float* __restrict__ pe, float* __restrict__ x) {
    int idx = blockIdx.x * 256 + threadIdx.x;
    if (idx >= NTOK * DMODEL) return;
    int row = idx >> 10;
    int d = idx & 1023;
    int s = row & (SEQ - 1);
    x[idx] = emb[(size_t)tokens[row] * DMODEL + d] * 32.0f + pe[(s << 10) + d];
}

// ---------------- layernorm (SPLIT=1 -> fp16 hi/lo; 0 -> fp32) ----------------
template <int SPLIT>
__global__ void __launch_bounds__(256) ln_kernel(const float* __restrict__ in,
                                                 const float* __restrict__ g,
                                                 const float* __restrict__ b,
                                                 float* __restrict__ outf,
                                                 fp16* __restrict__ oh, fp16* __restrict__ ol) {
    int row = blockIdx.x;
    const float* xr = in + (size_t)row * DMODEL;
    float v[4];
    float s = 0.f, s2 = 0.f;
#pragma unroll
    for (int i = 0; i < 4; i++) {
        v[i] = xr[threadIdx.x + i * 256];
        s += v[i]; s2 += v[i] * v[i];
    }
    __shared__ float rs[8], rs2[8];
#pragma unroll
    for (int off = 16; off; off >>= 1) {
        s  += __shfl_xor_sync(0xffffffffu, s, off);
        s2 += __shfl_xor_sync(0xffffffffu, s2, off);
    }
    if ((threadIdx.x & 31) == 0) { rs[threadIdx.x >> 5] = s; rs2[threadIdx.x >> 5] = s2; }
    __syncthreads();
    if (threadIdx.x < 32) {
        s  = (threadIdx.x < 8) ? rs[threadIdx.x] : 0.f;
        s2 = (threadIdx.x < 8) ? rs2[threadIdx.x] : 0.f;
#pragma unroll
        for (int off = 4; off; off >>= 1) {
            s  += __shfl_xor_sync(0xffffffffu, s, off);
            s2 += __shfl_xor_sync(0xffffffffu, s2, off);
        }
        if (threadIdx.x == 0) { rs[0] = s; rs2[0] = s2; }
    }
    __syncthreads();
    float m = rs[0] * (1.f / DMODEL);
    float var = rs2[0] * (1.f / DMODEL) - m * m;
    float rstd = rsqrtf(var + 1e-5f);
#pragma unroll
    for (int i = 0; i < 4; i++) {
        int c = threadIdx.x + i * 256;
        float val = (v[i] - m) * rstd * g[c] + b[c];
        if (SPLIT) {
            fp16 h = __float2half_rn(val);
            oh[(size_t)row * DMODEL + c] = h;
            ol[(size_t)row * DMODEL + c] = __float2half_rn(val - __half2float(h));
        } else {
            outf[(size_t)row * DMODEL + c] = val;
        }
    }
}

// ---------------- host ----------------
extern "C" void kernel_launch(void* const* d_in, const int* in_sizes, int n_in,
                              void* d_out, int out_size) {
    const int*   tokens = (const int*)  d_in[0];
    const int*   lengths= (const int*)  d_in[1];
    const float* emb    = (const float*)d_in[2];
    const float* Wq     = (const float*)d_in[3];
    const float* bq     = (const float*)d_in[4];
    const float* Wkv    = (const float*)d_in[5];
    const float* bkv    = (const float*)d_in[6];
    const float* Wo     = (const float*)d_in[7];
    const float* bo     = (const float*)d_in[8];
    const float* lag    = (const float*)d_in[9];
    const float* lab    = (const float*)d_in[10];
    const float* W1     = (const float*)d_in[11];
    const float* b1     = (const float*)d_in[12];
    const float* W2     = (const float*)d_in[13];
    const float* b2     = (const float*)d_in[14];
    const float* lfg    = (const float*)d_in[15];
    const float* lfb    = (const float*)d_in[16];
    const float* lng    = (const float*)d_in[17];
    const float* lnb    = (const float*)d_in[18];

    float *x, *pe;
    fp16 *q16, *kv16, *hh, *hl, *oh, *ol, *fh, *fl;
    fp16 *wqT, *wkvT, *woT, *w1T, *w2T;
    cudaGetSymbolAddress((void**)&x, g_x);
    cudaGetSymbolAddress((void**)&pe, g_pe);
    cudaGetSymbolAddress((void**)&q16, g_q16);
    cudaGetSymbolAddress((void**)&kv16, g_kv16);
    cudaGetSymbolAddress((void**)&hh, g_hh);
    cudaGetSymbolAddress((void**)&hl, g_hl);
    cudaGetSymbolAddress((void**)&oh, g_oh);
    cudaGetSymbolAddress((void**)&ol, g_ol);
    cudaGetSymbolAddress((void**)&fh, g_fh);
    cudaGetSymbolAddress((void**)&fl, g_fl);
    cudaGetSymbolAddress((void**)&wqT, g_wqT);
    cudaGetSymbolAddress((void**)&wkvT, g_wkvT);
    cudaGetSymbolAddress((void**)&woT, g_woT);
    cudaGetSymbolAddress((void**)&w1T, g_w1T);
    cudaGetSymbolAddress((void**)&w2T, g_w2T);

    cudaFuncSetAttribute(tgemm<0>, cudaFuncAttributeMaxDynamicSharedMemorySize, SMEM_T);
    cudaFuncSetAttribute(tgemm<1>, cudaFuncAttributeMaxDynamicSharedMemorySize, SMEM_T);
    cudaFuncSetAttribute(tgemm<2>, cudaFuncAttributeMaxDynamicSharedMemorySize, SMEM_T);
    cudaFuncSetAttribute(tgemm<3>, cudaFuncAttributeMaxDynamicSharedMemorySize, SMEM_T);
    cudaFuncSetAttribute(fattn, cudaFuncAttributeMaxDynamicSharedMemorySize, FA_SMEM);

    dim3 tb(32, 8);
    wsplit<<<dim3(DMODEL / 32, DMODEL / 32, NLAYER), tb>>>(Wq,  wqT,  DMODEL, DMODEL);
    wsplit<<<dim3(KVW / 32,    DMODEL / 32, NLAYER), tb>>>(Wkv, wkvT, DMODEL, KVW);
    wsplit<<<dim3(DMODEL / 32, DMODEL / 32, NLAYER), tb>>>(Wo,  woT,  DMODEL, DMODEL);
    wsplit<<<dim3(DFF / 32,    DMODEL / 32, NLAYER), tb>>>(W1,  w1T,  DMODEL, DFF);
    wsplit<<<dim3(DMODEL / 32, DFF / 32,    NLAYER), tb>>>(W2,  w2T,  DFF,    DMODEL);

    pe_kernel<<<(SEQ * DMODEL) / 256, 256>>>(pe);
    embed_kernel<<<(NTOK * DMODEL) / 256, 256>>>(tokens, emb, pe, x);

    for (int l = 0; l < NLAYER; l++) {
        size_t oQ  = (size_t)l * DMODEL * DMODEL;
        size_t oKV = (size_t)l * DMODEL * KVW;
        size_t o1w = (size_t)l * DMODEL * DFF;

        // attention sublayer
        ln_kernel<1><<<NTOK, 256>>>(x, lag + l * DMODEL, lab + l * DMODEL, nullptr, hh, hl);
        tgemm<3><<<dim3(DMODEL / 256, NTOK / 128), 256, SMEM_T>>>(
            hh, hl, wqT + oQ, bq + l * DMODEL, nullptr, q16, nullptr, DMODEL, DMODEL);
        tgemm<3><<<dim3(KVW / 256, NTOK / 128), 256, SMEM_T>>>(
            hh, hl, wkvT + oKV, bkv + l * KVW, nullptr, kv16, nullptr, KVW, DMODEL);
        fattn<<<dim3(SEQ / 128, BATCH * NHEAD), 256, FA_SMEM>>>(q16, kv16, lengths, oh, ol);
        tgemm<1><<<dim3(DMODEL / 256, NTOK / 128), 256, SMEM_T>>>(
            oh, ol, woT + oQ, bo + l * DMODEL, x, nullptr, nullptr, DMODEL, DMODEL);

        // FFN sublayer
        ln_kernel<1><<<NTOK, 256>>>(x, lfg + l * DMODEL, lfb + l * DMODEL, nullptr, hh, hl);
        tgemm<2><<<dim3(DFF / 256, NTOK / 128), 256, SMEM_T>>>(
            hh, hl, w1T + o1w, b1 + l * DFF, nullptr, fh, fl, DFF, DMODEL);
        tgemm<1><<<dim3(DMODEL / 256, NTOK / 128), 256, SMEM_T>>>(
            fh, fl, w2T + o1w, b2 + l * DMODEL, x, nullptr, nullptr, DMODEL, DFF);
    }

    ln_kernel<0><<<NTOK, 256>>>(x, lng, lnb, (float*)d_out, nullptr, nullptr);
}

// round 8
// speedup vs baseline: 5.0993x; 1.4728x over previous
#include <cuda_runtime.h>
#include <cuda_fp16.h>
#include <math.h>
#include <stdint.h>

// ---------------- problem dims ----------------
#define BATCH   8
#define SEQ     512
#define NTOK    4096
#define DMODEL  1024
#define NHEAD   16
#define DHEAD   64
#define DFF     4096
#define NLAYER  6
#define KVW     2048

typedef __half fp16;

// ---------------- scratch ----------------
__device__ float g_x [(size_t)NTOK * DMODEL];
__device__ float g_pe[(size_t)SEQ * DMODEL];

__device__ fp16 g_q16 [(size_t)NTOK * DMODEL];
__device__ fp16 g_kv16[(size_t)NTOK * KVW];

// fp16 activations (single precision digit)
__device__ fp16 g_h16[(size_t)NTOK * DMODEL];
__device__ fp16 g_o16[(size_t)NTOK * DMODEL];
__device__ fp16 g_f16[(size_t)NTOK * DFF];

// transposed weights: [N,K] fp16
__device__ fp16 g_wqT [(size_t)NLAYER * DMODEL * DMODEL];
__device__ fp16 g_wkvT[(size_t)NLAYER * DMODEL * KVW];
__device__ fp16 g_woT [(size_t)NLAYER * DMODEL * DMODEL];
__device__ fp16 g_w1T [(size_t)NLAYER * DMODEL * DFF];
__device__ fp16 g_w2T [(size_t)NLAYER * DFF * DMODEL];

// ---------------- helpers ----------------
__device__ __forceinline__ uint32_t smem_u32(const void* p) {
    uint32_t a;
    asm("{ .reg .u64 t; cvta.to.shared.u64 t, %1; cvt.u32.u64 %0, t; }" : "=r"(a) : "l"(p));
    return a;
}
#define CP_ASYNC16(dst, src) \
    asm volatile("cp.async.cg.shared.global [%0], [%1], 16;" :: "r"(dst), "l"(src) : "memory")
#define CP_COMMIT() asm volatile("cp.async.commit_group;" ::: "memory")
#define CP_WAIT2()  asm volatile("cp.async.wait_group 2;" ::: "memory")
#define CP_WAIT1()  asm volatile("cp.async.wait_group 1;" ::: "memory")
#define CP_WAIT0()  asm volatile("cp.async.wait_group 0;" ::: "memory")

__device__ __forceinline__ void ldsm4(uint32_t* r, uint32_t addr) {
    asm volatile("ldmatrix.sync.aligned.m8n8.x4.shared.b16 {%0,%1,%2,%3}, [%4];"
        : "=r"(r[0]), "=r"(r[1]), "=r"(r[2]), "=r"(r[3]) : "r"(addr));
}
__device__ __forceinline__ void mma_f16(float* d, const uint32_t* a, const uint32_t* b) {
    asm volatile("mma.sync.aligned.m16n8k16.row.col.f32.f16.f16.f32 "
        "{%0,%1,%2,%3}, {%4,%5,%6,%7}, {%8,%9}, {%0,%1,%2,%3};"
        : "+f"(d[0]), "+f"(d[1]), "+f"(d[2]), "+f"(d[3])
        : "r"(a[0]), "r"(a[1]), "r"(a[2]), "r"(a[3]), "r"(b[0]), "r"(b[1]));
}
__device__ __forceinline__ uint32_t pack_h2(float a, float b) {
    __half2 h = __halves2half2(__float2half_rn(a), __float2half_rn(b));
    return *(uint32_t*)&h;
}

// ---------------- fp16 1-pass GEMM: C[M,N] = A @ Bt^T ----------------
// CTA 128x256, 8 warps (2x4), warp tile 64x64, BK=32, 3-stage cp.async.
// MODE 1: fp32 +residual+bias; 2: relu -> fp16; 3: fp16
#define ROWB   80
#define OFF_A  0
#define OFF_B  10240
#define STAGE  30720
#define NSTAGE 3
#define SMEM_T (NSTAGE * STAGE)

template <int MODE>
__global__ void __launch_bounds__(256) tgemm(const fp16* __restrict__ Aa,
                                             const fp16* __restrict__ Bw,
                                             const float* __restrict__ bias,
                                             float* __restrict__ Cf,
                                             fp16* __restrict__ Ch,
                                             int N, int K) {
    extern __shared__ char smem[];
    const uint32_t sb = smem_u32(smem);
    const int tid  = threadIdx.x;
    const int wid  = tid >> 5, lane = tid & 31;
    const int wm   = wid >> 2, wn = wid & 3;
    const int bm   = blockIdx.y << 7;
    const int bn   = blockIdx.x << 8;
    const int T    = K >> 5;

    float acc[4][8][4] = {};

    auto load_stage = [&](int sidx, int k0) {
        uint32_t stg = sb + sidx * STAGE;
#pragma unroll
        for (int i = 0; i < 2; i++) {
            int flat = tid + i * 256;            // 0..511: A 128 rows x 4 chunks
            int r = flat >> 2, c = flat & 3;
            const fp16* src = Aa + (size_t)(bm + r) * K + k0 + c * 8;
            CP_ASYNC16(stg + OFF_A + r * ROWB + c * 16, src);
        }
#pragma unroll
        for (int i = 0; i < 4; i++) {
            int flat = tid + i * 256;            // 0..1023: B 256 rows x 4 chunks
            int r = flat >> 2, c = flat & 3;
            const fp16* src = Bw + (size_t)(bn + r) * K + k0 + c * 8;
            CP_ASYNC16(stg + OFF_B + r * ROWB + c * 16, src);
        }
        CP_COMMIT();
    };

    load_stage(0, 0);
    load_stage(1, 32);

    const int aRow  = lane & 15;
    const int aKc   = (lane >> 4) * 16;
    const int bNloc = ((lane >> 4) << 3) + (lane & 7);
    const int bKc   = ((lane >> 3) & 1) * 16;

    for (int it = 0; it < T; it++) {
        if (it + 2 < T) load_stage((it + 2) % NSTAGE, (it + 2) << 5);
        int remain = T - 1 - it;
        if (remain >= 2)      { CP_WAIT2(); }
        else if (remain == 1) { CP_WAIT1(); }
        else                  { CP_WAIT0(); }
        __syncthreads();

        uint32_t stg = sb + (it % NSTAGE) * STAGE;
        uint32_t aB = stg + OFF_A + (wm * 64 + aRow) * ROWB + aKc;
        uint32_t bB = stg + OFF_B + (wn * 64 + bNloc) * ROWB + bKc;

#pragma unroll
        for (int kk = 0; kk < 2; kk++) {
            uint32_t ka = kk * 32;
            uint32_t af[4][4], bf[8][2];
#pragma unroll
            for (int mi = 0; mi < 4; mi++)
                ldsm4(af[mi], aB + mi * 16 * ROWB + ka);
#pragma unroll
            for (int ni2 = 0; ni2 < 4; ni2++) {
                uint32_t r[4];
                ldsm4(r, bB + ni2 * 16 * ROWB + ka);
                bf[ni2 * 2][0] = r[0]; bf[ni2 * 2][1] = r[1];
                bf[ni2 * 2 + 1][0] = r[2]; bf[ni2 * 2 + 1][1] = r[3];
            }
#pragma unroll
            for (int mi = 0; mi < 4; mi++)
#pragma unroll
                for (int ni = 0; ni < 8; ni++)
                    mma_f16(acc[mi][ni], af[mi], bf[ni]);
        }
        __syncthreads();
    }

#pragma unroll
    for (int mi = 0; mi < 4; mi++) {
        int row0 = bm + wm * 64 + mi * 16 + (lane >> 2);
#pragma unroll
        for (int ni = 0; ni < 8; ni++) {
            int col = bn + wn * 64 + ni * 8 + (lane & 3) * 2;
            float b0 = bias[col], b1 = bias[col + 1];
#pragma unroll
            for (int half = 0; half < 2; half++) {
                int row = row0 + half * 8;
                float v0 = acc[mi][ni][half * 2]     + b0;
                float v1 = acc[mi][ni][half * 2 + 1] + b1;
                if (MODE == 2) {
                    v0 = fmaxf(v0, 0.f); v1 = fmaxf(v1, 0.f);
                    __half2 ph = __halves2half2(__float2half_rn(v0), __float2half_rn(v1));
                    *(uint32_t*)(Ch + (size_t)row * N + col) = *(uint32_t*)&ph;
                } else if (MODE == 3) {
                    __half2 ph = __halves2half2(__float2half_rn(v0), __float2half_rn(v1));
                    *(uint32_t*)(Ch + (size_t)row * N + col) = *(uint32_t*)&ph;
                } else {
                    float* dst = Cf + (size_t)row * N + col;
                    float v0r = v0 + dst[0], v1r = v1 + dst[1];
                    float2 o; o.x = v0r; o.y = v1r;
                    *(float2*)dst = o;
                }
            }
        }
    }
}

// ---------------- fused flash attention ----------------
// grid (SEQ/128, BATCH*NHEAD), 256 threads (8 warps x 16 q-rows)
#define FA_ROWB   144
#define FA_VTROWB 272
#define FA_Q   0
#define FA_K0  18432
#define FA_K1  36864
#define FA_V0  55296
#define FA_V1  73728
#define FA_VT  92160
#define FA_SMEM 109568

__global__ void __launch_bounds__(256) fattn(const fp16* __restrict__ Qf, const fp16* __restrict__ KVf,
                                             const int* __restrict__ lengths,
                                             fp16* __restrict__ oh) {
    extern __shared__ char smem[];
    const uint32_t sb = smem_u32(smem);
    const int tid = threadIdx.x, w = tid >> 5, lane = tid & 31;
    const int qb = blockIdx.x, bh = blockIdx.y;
    const int b = bh >> 4, h = bh & 15;
    const int len = lengths[b];
    const int tok0 = b * SEQ + qb * 128;

#pragma unroll
    for (int i = 0; i < 4; i++) {
        int flat = tid + i * 256; int r = flat >> 3, c = flat & 7;
        CP_ASYNC16(sb + FA_Q + r * FA_ROWB + c * 16, Qf + (size_t)(tok0 + r) * DMODEL + h * 64 + c * 8);
        CP_ASYNC16(sb + FA_K0 + r * FA_ROWB + c * 16, KVf + (size_t)(b * SEQ + r) * KVW + h * 64 + c * 8);
        CP_ASYNC16(sb + FA_V0 + r * FA_ROWB + c * 16, KVf + (size_t)(b * SEQ + r) * KVW + 1024 + h * 64 + c * 8);
    }
    CP_COMMIT();
#pragma unroll
    for (int i = 0; i < 4; i++) {
        int flat = tid + i * 256; int r = flat >> 3, c = flat & 7;
        CP_ASYNC16(sb + FA_K1 + r * FA_ROWB + c * 16, KVf + (size_t)(b * SEQ + 128 + r) * KVW + h * 64 + c * 8);
        CP_ASYNC16(sb + FA_V1 + r * FA_ROWB + c * 16, KVf + (size_t)(b * SEQ + 128 + r) * KVW + 1024 + h * 64 + c * 8);
    }
    CP_COMMIT();

    const int bNloc = ((lane >> 4) << 3) + (lane & 7);
    const int bKc   = ((lane >> 3) & 1) * 16;

    uint32_t qf[4][4];
    float O[8][4] = {};
    float m0 = -1e30f, m1 = -1e30f, l0 = 0.f, l1 = 0.f;

    for (int kb = 0; kb < 4; kb++) {
        if (kb < 3) { CP_WAIT1(); } else { CP_WAIT0(); }
        __syncthreads();

        if (kb == 0) {
            uint32_t qa = sb + FA_Q + (w * 16 + (lane & 15)) * FA_ROWB + (lane >> 4) * 16;
#pragma unroll
            for (int kc = 0; kc < 4; kc++) ldsm4(qf[kc], qa + kc * 32);
        }

        // transpose V(kb) -> VT [d][kpos]
        {
            const char* vsrcp = smem + ((kb & 1) ? FA_V1 : FA_V0);
            for (int idx = tid; idx < 4096; idx += 256) {
                int r = idx >> 5;
                int d2 = (idx & 31) << 1;
                __half2 vv = *reinterpret_cast<const __half2*>(vsrcp + r * FA_ROWB + d2 * 2);
                *reinterpret_cast<fp16*>(smem + FA_VT + (d2)     * FA_VTROWB + r * 2) = __low2half(vv);
                *reinterpret_cast<fp16*>(smem + FA_VT + (d2 + 1) * FA_VTROWB + r * 2) = __high2half(vv);
            }
        }
        __syncthreads();

        uint32_t koff = sb + ((kb & 1) ? FA_K1 : FA_K0);
        float p[16][4];
#pragma unroll
        for (int nt16 = 0; nt16 < 8; nt16++) {
            float s0[4] = {}, s1[4] = {};
#pragma unroll
            for (int kc = 0; kc < 4; kc++) {
                uint32_t r4[4];
                ldsm4(r4, koff + (nt16 * 16 + bNloc) * FA_ROWB + bKc + kc * 32);
                uint32_t bb0[2] = { r4[0], r4[1] }, bb1[2] = { r4[2], r4[3] };
                mma_f16(s0, qf[kc], bb0);
                mma_f16(s1, qf[kc], bb1);
            }
#pragma unroll
            for (int j = 0; j < 4; j++) { p[nt16 * 2][j] = s0[j]; p[nt16 * 2 + 1][j] = s1[j]; }
        }

        float mx0 = -1e30f, mx1 = -1e30f;
#pragma unroll
        for (int nt = 0; nt < 16; nt++) {
            int c = kb * 128 + nt * 8 + (lane & 3) * 2;
            float s0 = p[nt][0] * 0.125f, s1 = p[nt][1] * 0.125f;
            float s2 = p[nt][2] * 0.125f, s3 = p[nt][3] * 0.125f;
            if (c     >= len) { s0 = -1e30f; s2 = -1e30f; }
            if (c + 1 >= len) { s1 = -1e30f; s3 = -1e30f; }
            p[nt][0] = s0; p[nt][1] = s1; p[nt][2] = s2; p[nt][3] = s3;
            mx0 = fmaxf(mx0, fmaxf(s0, s1));
            mx1 = fmaxf(mx1, fmaxf(s2, s3));
        }
        mx0 = fmaxf(mx0, __shfl_xor_sync(0xffffffffu, mx0, 1));
        mx0 = fmaxf(mx0, __shfl_xor_sync(0xffffffffu, mx0, 2));
        mx1 = fmaxf(mx1, __shfl_xor_sync(0xffffffffu, mx1, 1));
        mx1 = fmaxf(mx1, __shfl_xor_sync(0xffffffffu, mx1, 2));
        float mn0 = fmaxf(m0, mx0), mn1 = fmaxf(m1, mx1);
        float corr0 = __expf(m0 - mn0), corr1 = __expf(m1 - mn1);
        m0 = mn0; m1 = mn1;
        float ls0 = 0.f, ls1 = 0.f;
#pragma unroll
        for (int nt = 0; nt < 16; nt++) {
            float e0 = __expf(p[nt][0] - mn0), e1 = __expf(p[nt][1] - mn0);
            float e2 = __expf(p[nt][2] - mn1), e3 = __expf(p[nt][3] - mn1);
            p[nt][0] = e0; p[nt][1] = e1; p[nt][2] = e2; p[nt][3] = e3;
            ls0 += e0 + e1; ls1 += e2 + e3;
        }
        l0 = l0 * corr0 + ls0;
        l1 = l1 * corr1 + ls1;
#pragma unroll
        for (int ni = 0; ni < 8; ni++) {
            O[ni][0] *= corr0; O[ni][1] *= corr0;
            O[ni][2] *= corr1; O[ni][3] *= corr1;
        }

#pragma unroll
        for (int kc = 0; kc < 8; kc++) {
            uint32_t pf[4];
            pf[0] = pack_h2(p[2 * kc][0],     p[2 * kc][1]);
            pf[1] = pack_h2(p[2 * kc][2],     p[2 * kc][3]);
            pf[2] = pack_h2(p[2 * kc + 1][0], p[2 * kc + 1][1]);
            pf[3] = pack_h2(p[2 * kc + 1][2], p[2 * kc + 1][3]);
#pragma unroll
            for (int nt16 = 0; nt16 < 4; nt16++) {
                uint32_t r4[4];
                ldsm4(r4, sb + FA_VT + (nt16 * 16 + bNloc) * FA_VTROWB + bKc + kc * 32);
                uint32_t bb0[2] = { r4[0], r4[1] }, bb1[2] = { r4[2], r4[3] };
                mma_f16(O[nt16 * 2], pf, bb0);
                mma_f16(O[nt16 * 2 + 1], pf, bb1);
            }
        }

        __syncthreads();
        if (kb < 2) {
            int blk = kb + 2;
            uint32_t kd = sb + ((blk & 1) ? FA_K1 : FA_K0);
            uint32_t vd = sb + ((blk & 1) ? FA_V1 : FA_V0);
#pragma unroll
            for (int i = 0; i < 4; i++) {
                int flat = tid + i * 256; int r = flat >> 3, c = flat & 7;
                CP_ASYNC16(kd + r * FA_ROWB + c * 16, KVf + (size_t)(b * SEQ + blk * 128 + r) * KVW + h * 64 + c * 8);
                CP_ASYNC16(vd + r * FA_ROWB + c * 16, KVf + (size_t)(b * SEQ + blk * 128 + r) * KVW + 1024 + h * 64 + c * 8);
            }
            CP_COMMIT();
        }
    }

    l0 += __shfl_xor_sync(0xffffffffu, l0, 1);
    l0 += __shfl_xor_sync(0xffffffffu, l0, 2);
    l1 += __shfl_xor_sync(0xffffffffu, l1, 1);
    l1 += __shfl_xor_sync(0xffffffffu, l1, 2);
    float inv0 = 1.f / l0, inv1 = 1.f / l1;
    int row0 = tok0 + w * 16 + (lane >> 2);
    int row1 = row0 + 8;
#pragma unroll
    for (int nt = 0; nt < 8; nt++) {
        int col = h * 64 + nt * 8 + (lane & 3) * 2;
        __half2 ph0 = __halves2half2(__float2half_rn(O[nt][0] * inv0), __float2half_rn(O[nt][1] * inv0));
        __half2 ph1 = __halves2half2(__float2half_rn(O[nt][2] * inv1), __float2half_rn(O[nt][3] * inv1));
        *(uint32_t*)(oh + (size_t)row0 * DMODEL + col) = *(uint32_t*)&ph0;
        *(uint32_t*)(oh + (size_t)row1 * DMODEL + col) = *(uint32_t*)&ph1;
    }
}

// ---------------- weight transpose to fp16 ----------------
__global__ void wsplit(const float* __restrict__ W, fp16* __restrict__ Tw, int K, int N) {
    __shared__ float t[32][33];
    const size_t lo = (size_t)blockIdx.z * K * N;
    const float* Wl = W + lo;
    fp16* tw = Tw + lo;
    int k0 = blockIdx.y << 5, n0 = blockIdx.x << 5;
    int tx = threadIdx.x, ty = threadIdx.y;
#pragma unroll
    for (int i = 0; i < 4; i++)
        t[ty + i * 8][tx] = Wl[(size_t)(k0 + ty + i * 8) * N + n0 + tx];
    __syncthreads();
#pragma unroll
    for (int i = 0; i < 4; i++) {
        size_t di = (size_t)(n0 + ty + i * 8) * K + k0 + tx;
        tw[di] = __float2half_rn(t[tx][ty + i * 8]);
    }
}

// ---------------- positional encoding ----------------
__global__ void pe_kernel(float* __restrict__ pe) {
    int idx = blockIdx.x * 256 + threadIdx.x;
    if (idx >= SEQ * DMODEL) return;
    int s = idx >> 10;
    int d = idx & 1023;
    double e = (double)(2 * (d >> 1)) / 1024.0;
    double ang = (double)s * exp(-e * log(10000.0));
    pe[idx] = (d & 1) ? (float)cos(ang) : (float)sin(ang);
}

// ---------------- embedding + PE ----------------
__global__ void embed_kernel(const int* __restrict__ tokens, const float* __restrict__ emb,
                             const float* __restrict__ pe, float* __restrict__ x) {
    int idx = blockIdx.x * 256 + threadIdx.x;
    if (idx >= NTOK * DMODEL) return;
    int row = idx >> 10;
    int d = idx & 1023;
    int s = row & (SEQ - 1);
    x[idx] = emb[(size_t)tokens[row] * DMODEL + d] * 32.0f + pe[(s << 10) + d];
}

// ---------------- layernorm (HALF=1 -> fp16 out; 0 -> fp32 out) ----------------
template <int HALF>
__global__ void __launch_bounds__(256) ln_kernel(const float* __restrict__ in,
                                                 const float* __restrict__ g,
                                                 const float* __restrict__ b,
                                                 float* __restrict__ outf,
                                                 fp16* __restrict__ oh) {
    int row = blockIdx.x;
    const float* xr = in + (size_t)row * DMODEL;
    float v[4];
    float s = 0.f, s2 = 0.f;
#pragma unroll
    for (int i = 0; i < 4; i++) {
        v[i] = xr[threadIdx.x + i * 256];
        s += v[i]; s2 += v[i] * v[i];
    }
    __shared__ float rs[8], rs2[8];
#pragma unroll
    for (int off = 16; off; off >>= 1) {
        s  += __shfl_xor_sync(0xffffffffu, s, off);
        s2 += __shfl_xor_sync(0xffffffffu, s2, off);
    }
    if ((threadIdx.x & 31) == 0) { rs[threadIdx.x >> 5] = s; rs2[threadIdx.x >> 5] = s2; }
    __syncthreads();
    if (threadIdx.x < 32) {
        s  = (threadIdx.x < 8) ? rs[threadIdx.x] : 0.f;
        s2 = (threadIdx.x < 8) ? rs2[threadIdx.x] : 0.f;
#pragma unroll
        for (int off = 4; off; off >>= 1) {
            s  += __shfl_xor_sync(0xffffffffu, s, off);
            s2 += __shfl_xor_sync(0xffffffffu, s2, off);
        }
        if (threadIdx.x == 0) { rs[0] = s; rs2[0] = s2; }
    }
    __syncthreads();
    float m = rs[0] * (1.f / DMODEL);
    float var = rs2[0] * (1.f / DMODEL) - m * m;
    float rstd = rsqrtf(var + 1e-5f);
#pragma unroll
    for (int i = 0; i < 4; i++) {
        int c = threadIdx.x + i * 256;
        float val = (v[i] - m) * rstd * g[c] + b[c];
        if (HALF) {
            oh[(size_t)row * DMODEL + c] = __float2half_rn(val);
        } else {
            outf[(size_t)row * DMODEL + c] = val;
        }
    }
}

// ---------------- host ----------------
extern "C" void kernel_launch(void* const* d_in, const int* in_sizes, int n_in,
                              void* d_out, int out_size) {
    const int*   tokens = (const int*)  d_in[0];
    const int*   lengths= (const int*)  d_in[1];
    const float* emb    = (const float*)d_in[2];
    const float* Wq     = (const float*)d_in[3];
    const float* bq     = (const float*)d_in[4];
    const float* Wkv    = (const float*)d_in[5];
    const float* bkv    = (const float*)d_in[6];
    const float* Wo     = (const float*)d_in[7];
    const float* bo     = (const float*)d_in[8];
    const float* lag    = (const float*)d_in[9];
    const float* lab    = (const float*)d_in[10];
    const float* W1     = (const float*)d_in[11];
    const float* b1     = (const float*)d_in[12];
    const float* W2     = (const float*)d_in[13];
    const float* b2     = (const float*)d_in[14];
    const float* lfg    = (const float*)d_in[15];
    const float* lfb    = (const float*)d_in[16];
    const float* lng    = (const float*)d_in[17];
    const float* lnb    = (const float*)d_in[18];

    float *x, *pe;
    fp16 *q16, *kv16, *h16, *o16, *f16;
    fp16 *wqT, *wkvT, *woT, *w1T, *w2T;
    cudaGetSymbolAddress((void**)&x, g_x);
    cudaGetSymbolAddress((void**)&pe, g_pe);
    cudaGetSymbolAddress((void**)&q16, g_q16);
    cudaGetSymbolAddress((void**)&kv16, g_kv16);
    cudaGetSymbolAddress((void**)&h16, g_h16);
    cudaGetSymbolAddress((void**)&o16, g_o16);
    cudaGetSymbolAddress((void**)&f16, g_f16);
    cudaGetSymbolAddress((void**)&wqT, g_wqT);
    cudaGetSymbolAddress((void**)&wkvT, g_wkvT);
    cudaGetSymbolAddress((void**)&woT, g_woT);
    cudaGetSymbolAddress((void**)&w1T, g_w1T);
    cudaGetSymbolAddress((void**)&w2T, g_w2T);

    cudaFuncSetAttribute(tgemm<1>, cudaFuncAttributeMaxDynamicSharedMemorySize, SMEM_T);
    cudaFuncSetAttribute(tgemm<2>, cudaFuncAttributeMaxDynamicSharedMemorySize, SMEM_T);
    cudaFuncSetAttribute(tgemm<3>, cudaFuncAttributeMaxDynamicSharedMemorySize, SMEM_T);
    cudaFuncSetAttribute(fattn, cudaFuncAttributeMaxDynamicSharedMemorySize, FA_SMEM);

    dim3 tb(32, 8);
    wsplit<<<dim3(DMODEL / 32, DMODEL / 32, NLAYER), tb>>>(Wq,  wqT,  DMODEL, DMODEL);
    wsplit<<<dim3(KVW / 32,    DMODEL / 32, NLAYER), tb>>>(Wkv, wkvT, DMODEL, KVW);
    wsplit<<<dim3(DMODEL / 32, DMODEL / 32, NLAYER), tb>>>(Wo,  woT,  DMODEL, DMODEL);
    wsplit<<<dim3(DFF / 32,    DMODEL / 32, NLAYER), tb>>>(W1,  w1T,  DMODEL, DFF);
    wsplit<<<dim3(DMODEL / 32, DFF / 32,    NLAYER), tb>>>(W2,  w2T,  DFF,    DMODEL);

    pe_kernel<<<(SEQ * DMODEL) / 256, 256>>>(pe);
    embed_kernel<<<(NTOK * DMODEL) / 256, 256>>>(tokens, emb, pe, x);

    for (int l = 0; l < NLAYER; l++) {
        size_t oQ  = (size_t)l * DMODEL * DMODEL;
        size_t oKV = (size_t)l * DMODEL * KVW;
        size_t o1w = (size_t)l * DMODEL * DFF;

        // attention sublayer
        ln_kernel<1><<<NTOK, 256>>>(x, lag + l * DMODEL, lab + l * DMODEL, nullptr, h16);
        tgemm<3><<<dim3(DMODEL / 256, NTOK / 128), 256, SMEM_T>>>(
            h16, wqT + oQ, bq + l * DMODEL, nullptr, q16, DMODEL, DMODEL);
        tgemm<3><<<dim3(KVW / 256, NTOK / 128), 256, SMEM_T>>>(
            h16, wkvT + oKV, bkv + l * KVW, nullptr, kv16, KVW, DMODEL);
        fattn<<<dim3(SEQ / 128, BATCH * NHEAD), 256, FA_SMEM>>>(q16, kv16, lengths, o16);
        tgemm<1><<<dim3(DMODEL / 256, NTOK / 128), 256, SMEM_T>>>(
            o16, woT + oQ, bo + l * DMODEL, x, nullptr, DMODEL, DMODEL);

        // FFN sublayer
        ln_kernel<1><<<NTOK, 256>>>(x, lfg + l * DMODEL, lfb + l * DMODEL, nullptr, h16);
        tgemm<2><<<dim3(DFF / 256, NTOK / 128), 256, SMEM_T>>>(
            h16, w1T + o1w, b1 + l * DFF, nullptr, f16, DFF, DMODEL);
        tgemm<1><<<dim3(DMODEL / 256, NTOK / 128), 256, SMEM_T>>>(
            f16, w2T + o1w, b2 + l * DMODEL, x, nullptr, DMODEL, DFF);
    }

    ln_kernel<0><<<NTOK, 256>>>(x, lng, lnb, (float*)d_out, nullptr);
}

// round 9
// speedup vs baseline: 5.3208x; 1.0434x over previous
#include <cuda_runtime.h>
#include <cuda_fp16.h>
#include <math.h>
#include <stdint.h>

// ---------------- problem dims ----------------
#define BATCH   8
#define SEQ     512
#define NTOK    4096
#define DMODEL  1024
#define NHEAD   16
#define DHEAD   64
#define DFF     4096
#define NLAYER  6
#define KVW     2048
#define QKVW    3072

typedef __half fp16;

// ---------------- scratch ----------------
__device__ float g_x [(size_t)NTOK * DMODEL];
__device__ float g_pe[(size_t)SEQ * DMODEL];

__device__ fp16 g_qkv16[(size_t)NTOK * QKVW];
__device__ fp16 g_h16[(size_t)NTOK * DMODEL];
__device__ fp16 g_o16[(size_t)NTOK * DMODEL];
__device__ fp16 g_f16[(size_t)NTOK * DFF];

// transposed weights: [N,K] fp16
__device__ fp16 g_wqkvT[(size_t)NLAYER * DMODEL * QKVW];
__device__ fp16 g_woT [(size_t)NLAYER * DMODEL * DMODEL];
__device__ fp16 g_w1T [(size_t)NLAYER * DMODEL * DFF];
__device__ fp16 g_w2T [(size_t)NLAYER * DFF * DMODEL];
__device__ float g_bqkv[(size_t)NLAYER * QKVW];

// ---------------- helpers ----------------
__device__ __forceinline__ uint32_t smem_u32(const void* p) {
    uint32_t a;
    asm("{ .reg .u64 t; cvta.to.shared.u64 t, %1; cvt.u32.u64 %0, t; }" : "=r"(a) : "l"(p));
    return a;
}
#define CP_ASYNC16(dst, src) \
    asm volatile("cp.async.cg.shared.global [%0], [%1], 16;" :: "r"(dst), "l"(src) : "memory")
#define CP_COMMIT() asm volatile("cp.async.commit_group;" ::: "memory")
#define CP_WAIT2()  asm volatile("cp.async.wait_group 2;" ::: "memory")
#define CP_WAIT1()  asm volatile("cp.async.wait_group 1;" ::: "memory")
#define CP_WAIT0()  asm volatile("cp.async.wait_group 0;" ::: "memory")

__device__ __forceinline__ void ldsm4(uint32_t* r, uint32_t addr) {
    asm volatile("ldmatrix.sync.aligned.m8n8.x4.shared.b16 {%0,%1,%2,%3}, [%4];"
        : "=r"(r[0]), "=r"(r[1]), "=r"(r[2]), "=r"(r[3]) : "r"(addr));
}
__device__ __forceinline__ void ldsm4t(uint32_t* r, uint32_t addr) {
    asm volatile("ldmatrix.sync.aligned.m8n8.x4.trans.shared.b16 {%0,%1,%2,%3}, [%4];"
        : "=r"(r[0]), "=r"(r[1]), "=r"(r[2]), "=r"(r[3]) : "r"(addr));
}
__device__ __forceinline__ void mma_f16(float* d, const uint32_t* a, const uint32_t* b) {
    asm volatile("mma.sync.aligned.m16n8k16.row.col.f32.f16.f16.f32 "
        "{%0,%1,%2,%3}, {%4,%5,%6,%7}, {%8,%9}, {%0,%1,%2,%3};"
        : "+f"(d[0]), "+f"(d[1]), "+f"(d[2]), "+f"(d[3])
        : "r"(a[0]), "r"(a[1]), "r"(a[2]), "r"(a[3]), "r"(b[0]), "r"(b[1]));
}
__device__ __forceinline__ uint32_t pack_h2(float a, float b) {
    __half2 h = __halves2half2(__float2half_rn(a), __float2half_rn(b));
    return *(uint32_t*)&h;
}

// ---------------- fp16 1-pass GEMM: C[M,N] = A @ Bt^T ----------------
// CTA 128x256, 8 warps (2x4), warp tile 64x64, BK=32, 3-stage cp.async.
// MODE 1: fp32 +residual+bias; 2: relu -> fp16; 3: fp16
#define ROWB   80
#define OFF_A  0
#define OFF_B  10240
#define STAGE  30720
#define NSTAGE 3
#define SMEM_T (NSTAGE * STAGE)

template <int MODE>
__global__ void __launch_bounds__(256) tgemm(const fp16* __restrict__ Aa,
                                             const fp16* __restrict__ Bw,
                                             const float* __restrict__ bias,
                                             float* __restrict__ Cf,
                                             fp16* __restrict__ Ch,
                                             int N, int K) {
    extern __shared__ char smem[];
    const uint32_t sb = smem_u32(smem);
    const int tid  = threadIdx.x;
    const int wid  = tid >> 5, lane = tid & 31;
    const int wm   = wid >> 2, wn = wid & 3;
    const int bm   = blockIdx.y << 7;
    const int bn   = blockIdx.x << 8;
    const int T    = K >> 5;

    float acc[4][8][4] = {};

    auto load_stage = [&](int sidx, int k0) {
        uint32_t stg = sb + sidx * STAGE;
#pragma unroll
        for (int i = 0; i < 2; i++) {
            int flat = tid + i * 256;
            int r = flat >> 2, c = flat & 3;
            const fp16* src = Aa + (size_t)(bm + r) * K + k0 + c * 8;
            CP_ASYNC16(stg + OFF_A + r * ROWB + c * 16, src);
        }
#pragma unroll
        for (int i = 0; i < 4; i++) {
            int flat = tid + i * 256;
            int r = flat >> 2, c = flat & 3;
            const fp16* src = Bw + (size_t)(bn + r) * K + k0 + c * 8;
            CP_ASYNC16(stg + OFF_B + r * ROWB + c * 16, src);
        }
        CP_COMMIT();
    };

    load_stage(0, 0);
    load_stage(1, 32);

    const int aRow  = lane & 15;
    const int aKc   = (lane >> 4) * 16;
    const int bNloc = ((lane >> 4) << 3) + (lane & 7);
    const int bKc   = ((lane >> 3) & 1) * 16;

    for (int it = 0; it < T; it++) {
        if (it + 2 < T) load_stage((it + 2) % NSTAGE, (it + 2) << 5);
        int remain = T - 1 - it;
        if (remain >= 2)      { CP_WAIT2(); }
        else if (remain == 1) { CP_WAIT1(); }
        else                  { CP_WAIT0(); }
        __syncthreads();

        uint32_t stg = sb + (it % NSTAGE) * STAGE;
        uint32_t aB = stg + OFF_A + (wm * 64 + aRow) * ROWB + aKc;
        uint32_t bB = stg + OFF_B + (wn * 64 + bNloc) * ROWB + bKc;

#pragma unroll
        for (int kk = 0; kk < 2; kk++) {
            uint32_t ka = kk * 32;
            uint32_t af[4][4], bf[8][2];
#pragma unroll
            for (int mi = 0; mi < 4; mi++)
                ldsm4(af[mi], aB + mi * 16 * ROWB + ka);
#pragma unroll
            for (int ni2 = 0; ni2 < 4; ni2++) {
                uint32_t r[4];
                ldsm4(r, bB + ni2 * 16 * ROWB + ka);
                bf[ni2 * 2][0] = r[0]; bf[ni2 * 2][1] = r[1];
                bf[ni2 * 2 + 1][0] = r[2]; bf[ni2 * 2 + 1][1] = r[3];
            }
#pragma unroll
            for (int mi = 0; mi < 4; mi++)
#pragma unroll
                for (int ni = 0; ni < 8; ni++)
                    mma_f16(acc[mi][ni], af[mi], bf[ni]);
        }
        __syncthreads();
    }

#pragma unroll
    for (int mi = 0; mi < 4; mi++) {
        int row0 = bm + wm * 64 + mi * 16 + (lane >> 2);
#pragma unroll
        for (int ni = 0; ni < 8; ni++) {
            int col = bn + wn * 64 + ni * 8 + (lane & 3) * 2;
            float b0 = bias[col], b1 = bias[col + 1];
#pragma unroll
            for (int half = 0; half < 2; half++) {
                int row = row0 + half * 8;
                float v0 = acc[mi][ni][half * 2]     + b0;
                float v1 = acc[mi][ni][half * 2 + 1] + b1;
                if (MODE == 2) {
                    v0 = fmaxf(v0, 0.f); v1 = fmaxf(v1, 0.f);
                    __half2 ph = __halves2half2(__float2half_rn(v0), __float2half_rn(v1));
                    *(uint32_t*)(Ch + (size_t)row * N + col) = *(uint32_t*)&ph;
                } else if (MODE == 3) {
                    __half2 ph = __halves2half2(__float2half_rn(v0), __float2half_rn(v1));
                    *(uint32_t*)(Ch + (size_t)row * N + col) = *(uint32_t*)&ph;
                } else {
                    float* dst = Cf + (size_t)row * N + col;
                    float v0r = v0 + dst[0], v1r = v1 + dst[1];
                    float2 o; o.x = v0r; o.y = v1r;
                    *(float2*)dst = o;
                }
            }
        }
    }
}

// ---------------- fused flash attention (trans-V, fused QKV input) ----------------
// grid (SEQ/128, BATCH*NHEAD), 256 threads (8 warps x 16 q-rows)
#define FA_ROWB  144
#define FA_Q   0
#define FA_K0  18432
#define FA_K1  36864
#define FA_V0  55296
#define FA_V1  73728
#define FA_SMEM 92160

__global__ void __launch_bounds__(256) fattn(const fp16* __restrict__ QKV,
                                             const int* __restrict__ lengths,
                                             fp16* __restrict__ oh) {
    extern __shared__ char smem[];
    const uint32_t sb = smem_u32(smem);
    const int tid = threadIdx.x, w = tid >> 5, lane = tid & 31;
    const int qb = blockIdx.x, bh = blockIdx.y;
    const int b = bh >> 4, h = bh & 15;
    const int len = lengths[b];
    const int tok0 = b * SEQ + qb * 128;

#pragma unroll
    for (int i = 0; i < 4; i++) {
        int flat = tid + i * 256; int r = flat >> 3, c = flat & 7;
        CP_ASYNC16(sb + FA_Q + r * FA_ROWB + c * 16,  QKV + (size_t)(tok0 + r) * QKVW + h * 64 + c * 8);
        CP_ASYNC16(sb + FA_K0 + r * FA_ROWB + c * 16, QKV + (size_t)(b * SEQ + r) * QKVW + 1024 + h * 64 + c * 8);
        CP_ASYNC16(sb + FA_V0 + r * FA_ROWB + c * 16, QKV + (size_t)(b * SEQ + r) * QKVW + 2048 + h * 64 + c * 8);
    }
    CP_COMMIT();
#pragma unroll
    for (int i = 0; i < 4; i++) {
        int flat = tid + i * 256; int r = flat >> 3, c = flat & 7;
        CP_ASYNC16(sb + FA_K1 + r * FA_ROWB + c * 16, QKV + (size_t)(b * SEQ + 128 + r) * QKVW + 1024 + h * 64 + c * 8);
        CP_ASYNC16(sb + FA_V1 + r * FA_ROWB + c * 16, QKV + (size_t)(b * SEQ + 128 + r) * QKVW + 2048 + h * 64 + c * 8);
    }
    CP_COMMIT();

    const int bNloc = ((lane >> 4) << 3) + (lane & 7);
    const int bKc   = ((lane >> 3) & 1) * 16;
    // trans-V per-lane offset: matrix m = lane>>3, row i = lane&7
    const int vg = lane >> 3, vi = lane & 7;
    const uint32_t vOff = (uint32_t)(((vg & 1) * 8 + vi) * FA_ROWB + (vg >> 1) * 16);

    uint32_t qf[4][4];
    float O[8][4] = {};
    float m0 = -1e30f, m1 = -1e30f, l0 = 0.f, l1 = 0.f;

    for (int kb = 0; kb < 4; kb++) {
        if (kb < 3) { CP_WAIT1(); } else { CP_WAIT0(); }
        __syncthreads();

        if (kb == 0) {
            uint32_t qa = sb + FA_Q + (w * 16 + (lane & 15)) * FA_ROWB + (lane >> 4) * 16;
#pragma unroll
            for (int kc = 0; kc < 4; kc++) ldsm4(qf[kc], qa + kc * 32);
        }

        // ---- QK^T ----
        uint32_t koff = sb + ((kb & 1) ? FA_K1 : FA_K0);
        float p[16][4];
#pragma unroll
        for (int nt16 = 0; nt16 < 8; nt16++) {
            float s0[4] = {}, s1[4] = {};
#pragma unroll
            for (int kc = 0; kc < 4; kc++) {
                uint32_t r4[4];
                ldsm4(r4, koff + (nt16 * 16 + bNloc) * FA_ROWB + bKc + kc * 32);
                uint32_t bb0[2] = { r4[0], r4[1] }, bb1[2] = { r4[2], r4[3] };
                mma_f16(s0, qf[kc], bb0);
                mma_f16(s1, qf[kc], bb1);
            }
#pragma unroll
            for (int j = 0; j < 4; j++) { p[nt16 * 2][j] = s0[j]; p[nt16 * 2 + 1][j] = s1[j]; }
        }

        // ---- mask + online softmax ----
        float mx0 = -1e30f, mx1 = -1e30f;
#pragma unroll
        for (int nt = 0; nt < 16; nt++) {
            int c = kb * 128 + nt * 8 + (lane & 3) * 2;
            float s0 = p[nt][0] * 0.125f, s1 = p[nt][1] * 0.125f;
            float s2 = p[nt][2] * 0.125f, s3 = p[nt][3] * 0.125f;
            if (c     >= len) { s0 = -1e30f; s2 = -1e30f; }
            if (c + 1 >= len) { s1 = -1e30f; s3 = -1e30f; }
            p[nt][0] = s0; p[nt][1] = s1; p[nt][2] = s2; p[nt][3] = s3;
            mx0 = fmaxf(mx0, fmaxf(s0, s1));
            mx1 = fmaxf(mx1, fmaxf(s2, s3));
        }
        mx0 = fmaxf(mx0, __shfl_xor_sync(0xffffffffu, mx0, 1));
        mx0 = fmaxf(mx0, __shfl_xor_sync(0xffffffffu, mx0, 2));
        mx1 = fmaxf(mx1, __shfl_xor_sync(0xffffffffu, mx1, 1));
        mx1 = fmaxf(mx1, __shfl_xor_sync(0xffffffffu, mx1, 2));
        float mn0 = fmaxf(m0, mx0), mn1 = fmaxf(m1, mx1);
        float corr0 = __expf(m0 - mn0), corr1 = __expf(m1 - mn1);
        m0 = mn0; m1 = mn1;
        float ls0 = 0.f, ls1 = 0.f;
#pragma unroll
        for (int nt = 0; nt < 16; nt++) {
            float e0 = __expf(p[nt][0] - mn0), e1 = __expf(p[nt][1] - mn0);
            float e2 = __expf(p[nt][2] - mn1), e3 = __expf(p[nt][3] - mn1);
            p[nt][0] = e0; p[nt][1] = e1; p[nt][2] = e2; p[nt][3] = e3;
            ls0 += e0 + e1; ls1 += e2 + e3;
        }
        l0 = l0 * corr0 + ls0;
        l1 = l1 * corr1 + ls1;
#pragma unroll
        for (int ni = 0; ni < 8; ni++) {
            O[ni][0] *= corr0; O[ni][1] *= corr0;
            O[ni][2] *= corr1; O[ni][3] *= corr1;
        }

        // ---- P @ V (trans-V fragments directly from row-major V tile) ----
        uint32_t vbase = sb + ((kb & 1) ? FA_V1 : FA_V0) + vOff;
#pragma unroll
        for (int kc = 0; kc < 8; kc++) {
            uint32_t pf[4];
            pf[0] = pack_h2(p[2 * kc][0],     p[2 * kc][1]);
            pf[1] = pack_h2(p[2 * kc][2],     p[2 * kc][3]);
            pf[2] = pack_h2(p[2 * kc + 1][0], p[2 * kc + 1][1]);
            pf[3] = pack_h2(p[2 * kc + 1][2], p[2 * kc + 1][3]);
#pragma unroll
            for (int nt16 = 0; nt16 < 4; nt16++) {
                uint32_t r4[4];
                ldsm4t(r4, vbase + kc * 16 * FA_ROWB + nt16 * 32);
                uint32_t bb0[2] = { r4[0], r4[1] }, bb1[2] = { r4[2], r4[3] };
                mma_f16(O[nt16 * 2], pf, bb0);
                mma_f16(O[nt16 * 2 + 1], pf, bb1);
            }
        }

        __syncthreads();
        if (kb < 2) {
            int blk = kb + 2;
            uint32_t kd = sb + ((blk & 1) ? FA_K1 : FA_K0);
            uint32_t vd = sb + ((blk & 1) ? FA_V1 : FA_V0);
#pragma unroll
            for (int i = 0; i < 4; i++) {
                int flat = tid + i * 256; int r = flat >> 3, c = flat & 7;
                CP_ASYNC16(kd + r * FA_ROWB + c * 16, QKV + (size_t)(b * SEQ + blk * 128 + r) * QKVW + 1024 + h * 64 + c * 8);
                CP_ASYNC16(vd + r * FA_ROWB + c * 16, QKV + (size_t)(b * SEQ + blk * 128 + r) * QKVW + 2048 + h * 64 + c * 8);
            }
            CP_COMMIT();
        }
    }

    l0 += __shfl_xor_sync(0xffffffffu, l0, 1);
    l0 += __shfl_xor_sync(0xffffffffu, l0, 2);
    l1 += __shfl_xor_sync(0xffffffffu, l1, 1);
    l1 += __shfl_xor_sync(0xffffffffu, l1, 2);
    float inv0 = 1.f / l0, inv1 = 1.f / l1;
    int row0 = tok0 + w * 16 + (lane >> 2);
    int row1 = row0 + 8;
#pragma unroll
    for (int nt = 0; nt < 8; nt++) {
        int col = h * 64 + nt * 8 + (lane & 3) * 2;
        __half2 ph0 = __halves2half2(__float2half_rn(O[nt][0] * inv0), __float2half_rn(O[nt][1] * inv0));
        __half2 ph1 = __halves2half2(__float2half_rn(O[nt][2] * inv1), __float2half_rn(O[nt][3] * inv1));
        *(uint32_t*)(oh + (size_t)row0 * DMODEL + col) = *(uint32_t*)&ph0;
        *(uint32_t*)(oh + (size_t)row1 * DMODEL + col) = *(uint32_t*)&ph1;
    }
}

// ---------------- weight transpose to fp16 (into combined/strided dst) ----------------
__global__ void wsplit(const float* __restrict__ W, fp16* __restrict__ Tw,
                       int K, int N, int ldRows, int roff) {
    __shared__ float t[32][33];
    const float* Wl = W + (size_t)blockIdx.z * K * N;
    fp16* tw = Tw + (size_t)blockIdx.z * K * ldRows;
    int k0 = blockIdx.y << 5, n0 = blockIdx.x << 5;
    int tx = threadIdx.x, ty = threadIdx.y;
#pragma unroll
    for (int i = 0; i < 4; i++)
        t[ty + i * 8][tx] = Wl[(size_t)(k0 + ty + i * 8) * N + n0 + tx];
    __syncthreads();
#pragma unroll
    for (int i = 0; i < 4; i++) {
        size_t di = (size_t)(roff + n0 + ty + i * 8) * K + k0 + tx;
        tw[di] = __float2half_rn(t[tx][ty + i * 8]);
    }
}

// ---------------- concat QKV bias ----------------
__global__ void bcat(const float* __restrict__ bq, const float* __restrict__ bkv,
                     float* __restrict__ bqkv) {
    int idx = blockIdx.x * 256 + threadIdx.x;
    if (idx >= NLAYER * QKVW) return;
    int l = idx / QKVW, j = idx % QKVW;
    bqkv[idx] = (j < DMODEL) ? bq[l * DMODEL + j] : bkv[l * KVW + j - DMODEL];
}

// ---------------- positional encoding ----------------
__global__ void pe_kernel(float* __restrict__ pe) {
    int idx = blockIdx.x * 256 + threadIdx.x;
    if (idx >= SEQ * DMODEL) return;
    int s = idx >> 10;
    int d = idx & 1023;
    double e = (double)(2 * (d >> 1)) / 1024.0;
    double ang = (double)s * exp(-e * log(10000.0));
    pe[idx] = (d & 1) ? (float)cos(ang) : (float)sin(ang);
}

// ---------------- embedding + PE ----------------
__global__ void embed_kernel(const int* __restrict__ tokens, const float* __restrict__ emb,
                             const float* __restrict__ pe, float* __restrict__ x) {
    int idx = blockIdx.x * 256 + threadIdx.x;
    if (idx >= NTOK * DMODEL) return;
    int row = idx >> 10;
    int d = idx & 1023;
    int s = row & (SEQ - 1);
    x[idx] = emb[(size_t)tokens[row] * DMODEL + d] * 32.0f + pe[(s << 10) + d];
}

// ---------------- layernorm, warp-per-row (HALF=1 -> fp16 out; 0 -> fp32) ----------------
template <int HALF>
__global__ void __launch_bounds__(256) ln_kernel(const float* __restrict__ in,
                                                 const float* __restrict__ g,
                                                 const float* __restrict__ b,
                                                 float* __restrict__ outf,
                                                 fp16* __restrict__ oh) {
    int row = blockIdx.x * 8 + (threadIdx.x >> 5);
    int lane = threadIdx.x & 31;
    const float* xr = in + (size_t)row * DMODEL;
    float4 v[8];
    float s = 0.f, s2 = 0.f;
#pragma unroll
    for (int i = 0; i < 8; i++) {
        v[i] = *(const float4*)(xr + lane * 4 + i * 128);
        s  += v[i].x + v[i].y + v[i].z + v[i].w;
        s2 += v[i].x * v[i].x + v[i].y * v[i].y + v[i].z * v[i].z + v[i].w * v[i].w;
    }
#pragma unroll
    for (int off = 16; off; off >>= 1) {
        s  += __shfl_xor_sync(0xffffffffu, s, off);
        s2 += __shfl_xor_sync(0xffffffffu, s2, off);
    }
    float m = s * (1.f / DMODEL);
    float var = s2 * (1.f / DMODEL) - m * m;
    float rstd = rsqrtf(var + 1e-5f);
#pragma unroll
    for (int i = 0; i < 8; i++) {
        int c = lane * 4 + i * 128;
        float4 gv = *(const float4*)(g + c);
        float4 bv = *(const float4*)(b + c);
        float o0 = (v[i].x - m) * rstd * gv.x + bv.x;
        float o1 = (v[i].y - m) * rstd * gv.y + bv.y;
        float o2 = (v[i].z - m) * rstd * gv.z + bv.z;
        float o3 = (v[i].w - m) * rstd * gv.w + bv.w;
        if (HALF) {
            uint2 pk;
            pk.x = pack_h2(o0, o1);
            pk.y = pack_h2(o2, o3);
            *(uint2*)(oh + (size_t)row * DMODEL + c) = pk;
        } else {
            float4 o; o.x = o0; o.y = o1; o.z = o2; o.w = o3;
            *(float4*)(outf + (size_t)row * DMODEL + c) = o;
        }
    }
}

// ---------------- host ----------------
extern "C" void kernel_launch(void* const* d_in, const int* in_sizes, int n_in,
                              void* d_out, int out_size) {
    const int*   tokens = (const int*)  d_in[0];
    const int*   lengths= (const int*)  d_in[1];
    const float* emb    = (const float*)d_in[2];
    const float* Wq     = (const float*)d_in[3];
    const float* bq     = (const float*)d_in[4];
    const float* Wkv    = (const float*)d_in[5];
    const float* bkv    = (const float*)d_in[6];
    const float* Wo     = (const float*)d_in[7];
    const float* bo     = (const float*)d_in[8];
    const float* lag    = (const float*)d_in[9];
    const float* lab    = (const float*)d_in[10];
    const float* W1     = (const float*)d_in[11];
    const float* b1     = (const float*)d_in[12];
    const float* W2     = (const float*)d_in[13];
    const float* b2     = (const float*)d_in[14];
    const float* lfg    = (const float*)d_in[15];
    const float* lfb    = (const float*)d_in[16];
    const float* lng    = (const float*)d_in[17];
    const float* lnb    = (const float*)d_in[18];

    float *x, *pe, *bqkv;
    fp16 *qkv16, *h16, *o16, *f16;
    fp16 *wqkvT, *woT, *w1T, *w2T;
    cudaGetSymbolAddress((void**)&x, g_x);
    cudaGetSymbolAddress((void**)&pe, g_pe);
    cudaGetSymbolAddress((void**)&qkv16, g_qkv16);
    cudaGetSymbolAddress((void**)&h16, g_h16);
    cudaGetSymbolAddress((void**)&o16, g_o16);
    cudaGetSymbolAddress((void**)&f16, g_f16);
    cudaGetSymbolAddress((void**)&wqkvT, g_wqkvT);
    cudaGetSymbolAddress((void**)&woT, g_woT);
    cudaGetSymbolAddress((void**)&w1T, g_w1T);
    cudaGetSymbolAddress((void**)&w2T, g_w2T);
    cudaGetSymbolAddress((void**)&bqkv, g_bqkv);

    cudaFuncSetAttribute(tgemm<1>, cudaFuncAttributeMaxDynamicSharedMemorySize, SMEM_T);
    cudaFuncSetAttribute(tgemm<2>, cudaFuncAttributeMaxDynamicSharedMemorySize, SMEM_T);
    cudaFuncSetAttribute(tgemm<3>, cudaFuncAttributeMaxDynamicSharedMemorySize, SMEM_T);
    cudaFuncSetAttribute(fattn, cudaFuncAttributeMaxDynamicSharedMemorySize, FA_SMEM);

    dim3 tb(32, 8);
    wsplit<<<dim3(DMODEL / 32, DMODEL / 32, NLAYER), tb>>>(Wq,  wqkvT, DMODEL, DMODEL, QKVW, 0);
    wsplit<<<dim3(KVW / 32,    DMODEL / 32, NLAYER), tb>>>(Wkv, wqkvT, DMODEL, KVW,   QKVW, DMODEL);
    wsplit<<<dim3(DMODEL / 32, DMODEL / 32, NLAYER), tb>>>(Wo,  woT,   DMODEL, DMODEL, DMODEL, 0);
    wsplit<<<dim3(DFF / 32,    DMODEL / 32, NLAYER), tb>>>(W1,  w1T,   DMODEL, DFF,   DFF, 0);
    wsplit<<<dim3(DMODEL / 32, DFF / 32,    NLAYER), tb>>>(W2,  w2T,   DFF,    DMODEL, DMODEL, 0);
    bcat<<<(NLAYER * QKVW + 255) / 256, 256>>>(bq, bkv, bqkv);

    pe_kernel<<<(SEQ * DMODEL) / 256, 256>>>(pe);
    embed_kernel<<<(NTOK * DMODEL) / 256, 256>>>(tokens, emb, pe, x);

    for (int l = 0; l < NLAYER; l++) {
        size_t oQKV = (size_t)l * DMODEL * QKVW;
        size_t oO   = (size_t)l * DMODEL * DMODEL;
        size_t o1w  = (size_t)l * DMODEL * DFF;

        // attention sublayer
        ln_kernel<1><<<NTOK / 8, 256>>>(x, lag + l * DMODEL, lab + l * DMODEL, nullptr, h16);
        tgemm<3><<<dim3(QKVW / 256, NTOK / 128), 256, SMEM_T>>>(
            h16, wqkvT + oQKV, bqkv + l * QKVW, nullptr, qkv16, QKVW, DMODEL);
        fattn<<<dim3(SEQ / 128, BATCH * NHEAD), 256, FA_SMEM>>>(qkv16, lengths, o16);
        tgemm<1><<<dim3(DMODEL / 256, NTOK / 128), 256, SMEM_T>>>(
            o16, woT + oO, bo + l * DMODEL, x, nullptr, DMODEL, DMODEL);

        // FFN sublayer
        ln_kernel<1><<<NTOK / 8, 256>>>(x, lfg + l * DMODEL, lfb + l * DMODEL, nullptr, h16);
        tgemm<2><<<dim3(DFF / 256, NTOK / 128), 256, SMEM_T>>>(
            h16, w1T + o1w, b1 + l * DFF, nullptr, f16, DFF, DMODEL);
        tgemm<1><<<dim3(DMODEL / 256, NTOK / 128), 256, SMEM_T>>>(
            f16, w2T + o1w, b2 + l * DMODEL, x, nullptr, DMODEL, DFF);
    }

    ln_kernel<0><<<NTOK / 8, 256>>>(x, lng, lnb, (float*)d_out, nullptr);
}